// round 14
// baseline (speedup 1.0000x reference)
#include <cuda_runtime.h>
#include <cuda_bf16.h>
#include <math.h>
#include <stdint.h>

// ---------------- problem constants ----------------
#define BATCH   2
#define SEQL    2048
#define DM      1024
#define DIN     2048      // D_INNER
#define DSTATE  128
#define NH      32
#define HD      64
#define DPROJ   4384      // D_IN_PROJ
#define CONVCH  2304      // D_INNER + 2*D_STATE
#define NCHUNK  16
#define CH      128
#define EPSV    1e-5f
#define ROWS    (BATCH*SEQL)   // 4096
#define NPADW   4480           // 35*128, padded N for widest weight

// ---------------- scratch (device globals; [2] = per direction) ----------------
__device__ float g_zx    [2][ROWS*DPROJ];
__device__ float g_xBC   [2][ROWS*CONVCH];
__device__ float g_dt    [2][ROWS*NH];
__device__ float g_Acs   [2][BATCH*NH*SEQL];
__device__ float g_states[2][BATCH*NCHUNK*NH*HD*DSTATE];
__device__ float g_prev  [2][BATCH*NCHUNK*NH*HD*DSTATE];
__device__ float g_S     [2][BATCH*NCHUNK*CH*CH];
__device__ float g_y     [2][ROWS*DIN];

__device__ __nv_bfloat16 g_XNhi[ROWS*DM];
__device__ __nv_bfloat16 g_XNlo[ROWS*DM];
__device__ __nv_bfloat16 g_Ahi [2][ROWS*DIN];
__device__ __nv_bfloat16 g_Alo [2][ROWS*DIN];
__device__ __nv_bfloat16 g_YChi[ROWS*2*DM];
__device__ __nv_bfloat16 g_YClo[ROWS*2*DM];
__device__ __nv_bfloat16 g_Whi [2][NPADW*DM];
__device__ __nv_bfloat16 g_Wlo [2][NPADW*DM];
__device__ __nv_bfloat16 g_WFhi[2*DM*DM];
__device__ __nv_bfloat16 g_WFlo[2*DM*DM];

// ---------------- asm helpers ----------------
__device__ __forceinline__ uint32_t smem_u32(const void* p) {
    uint32_t a;
    asm("{ .reg .u64 t; cvta.to.shared.u64 t, %1; cvt.u32.u64 %0, t; }" : "=r"(a) : "l"(p));
    return a;
}
#define CP16(d, s) asm volatile("cp.async.cg.shared.global [%0], [%1], 16;" :: "r"(d), "l"(s))
#define CP_COMMIT() asm volatile("cp.async.commit_group;")
#define LDSM4(r, a) asm volatile("ldmatrix.sync.aligned.m8n8.x4.shared.b16 {%0,%1,%2,%3}, [%4];" \
    : "=r"((r)[0]), "=r"((r)[1]), "=r"((r)[2]), "=r"((r)[3]) : "r"(a))
#define MMA16816(d, a, b) asm volatile( \
    "mma.sync.aligned.m16n8k16.row.col.f32.bf16.bf16.f32 " \
    "{%0,%1,%2,%3}, {%4,%5,%6,%7}, {%8,%9}, {%0,%1,%2,%3};" \
    : "+f"((d)[0]), "+f"((d)[1]), "+f"((d)[2]), "+f"((d)[3]) \
    : "r"((a)[0]), "r"((a)[1]), "r"((a)[2]), "r"((a)[3]), "r"((b)[0]), "r"((b)[1]))

__device__ __forceinline__ uint32_t sw_addr(uint32_t base, int row, int chunk) {
    return base + (uint32_t)row * 64u + ((((uint32_t)chunk) ^ (((uint32_t)row >> 1) & 3u)) << 4);
}

__device__ __forceinline__ void hilo(float v, __nv_bfloat16& h, __nv_bfloat16& l) {
    h = __float2bfloat16(v);
    l = __float2bfloat16(v - __bfloat162float(h));
}

// ---------------- fp32 -> bf16 hi/lo conversion (weights; with zero padding) ----------------
__global__ void k_cvt(const float* __restrict__ src, __nv_bfloat16* __restrict__ hi,
                      __nv_bfloat16* __restrict__ lo, long nvalid, long total) {
    long idx = ((long)blockIdx.x * 256 + threadIdx.x) * 8;
    if (idx >= total) return;
    uint4 hq = make_uint4(0, 0, 0, 0), lq = make_uint4(0, 0, 0, 0);
    if (idx < nvalid) {
        float4 f0 = *reinterpret_cast<const float4*>(src + idx);
        float4 f1 = *reinterpret_cast<const float4*>(src + idx + 4);
        float f[8] = {f0.x, f0.y, f0.z, f0.w, f1.x, f1.y, f1.z, f1.w};
        uint32_t h[8], l[8];
#pragma unroll
        for (int i = 0; i < 8; i++) {
            __nv_bfloat16 hb, lb; hilo(f[i], hb, lb);
            h[i] = __bfloat16_as_ushort(hb);
            l[i] = __bfloat16_as_ushort(lb);
        }
        hq.x = (h[1] << 16) | h[0]; hq.y = (h[3] << 16) | h[2];
        hq.z = (h[5] << 16) | h[4]; hq.w = (h[7] << 16) | h[6];
        lq.x = (l[1] << 16) | l[0]; lq.y = (l[3] << 16) | l[2];
        lq.z = (l[5] << 16) | l[4]; lq.w = (l[7] << 16) | l[6];
    }
    *reinterpret_cast<uint4*>(hi + idx) = hq;
    *reinterpret_cast<uint4*>(lo + idx) = lq;
}

// ---------------- HMMA GEMM (3-stage cp.async pipeline; batched A-frag loads) ----------------
#define HSMEM 98304

__global__ void __launch_bounds__(256, 2) k_hgemm(
    const __nv_bfloat16* __restrict__ Ahi, const __nv_bfloat16* __restrict__ Alo,
    int lda, int K, int flipA,
    const __nv_bfloat16* __restrict__ Whi, const __nv_bfloat16* __restrict__ Wlo,
    int ldw, int Ntot, float* __restrict__ C,
    __nv_bfloat16* __restrict__ Chi, __nv_bfloat16* __restrict__ Clo,
    int ldc, int flipC,
    const float* __restrict__ resid, const float* __restrict__ bias)
{
    extern __shared__ char smraw[];
    const uint32_t sb = smem_u32(smraw);
    const int tid = threadIdx.x, lane = tid & 31, wid = tid >> 5;
    const int bm = blockIdx.y * 128, bn = blockIdx.x * 128;
    const int wm = (wid & 1) * 64, wn = (wid >> 1) * 32;

    float acc[4][4][4];
#pragma unroll
    for (int i = 0; i < 4; i++)
#pragma unroll
        for (int j = 0; j < 4; j++)
#pragma unroll
            for (int k = 0; k < 4; k++) acc[i][j][k] = 0.f;

    const int ktiles = K / 32;

    auto load_stage = [&](int s, int k0) {
        uint32_t base = sb + s * 32768;
#pragma unroll
        for (int it = 0; it < 2; it++) {
            int q = tid + it * 256;
            int r = q >> 2, c = q & 3;
            int gr = bm + r, pr = gr;
            if (flipA) pr = (gr & ~(SEQL - 1)) + (SEQL - 1 - (gr & (SEQL - 1)));
            uint32_t d = sw_addr(base, r, c);
            size_t aoff = (size_t)pr * lda + k0 + c * 8;
            CP16(d,         (const char*)(Ahi + aoff));
            CP16(d + 8192,  (const char*)(Alo + aoff));
            size_t woff = (size_t)(bn + r) * ldw + k0 + c * 8;
            CP16(d + 16384, (const char*)(Whi + woff));
            CP16(d + 24576, (const char*)(Wlo + woff));
        }
        CP_COMMIT();
    };

    load_stage(0, 0);
    load_stage(1, 32);

    int stage = 0;
    for (int i = 0; i < ktiles; i++) {
        if (i == ktiles - 1) {
            asm volatile("cp.async.wait_group 0;");
        } else {
            asm volatile("cp.async.wait_group 1;");
        }
        __syncthreads();
        if (i + 2 < ktiles) {
            int ns = stage + 2; if (ns >= 3) ns -= 3;
            load_stage(ns, (i + 2) * 32);
        }
        uint32_t base = sb + stage * 32768;
#pragma unroll
        for (int ks = 0; ks < 2; ks++) {
            const int kb = ks * 2;
            uint32_t bh[4][2], bl[4][2];
#pragma unroll
            for (int p2 = 0; p2 < 2; p2++) {
                int rr = wn + p2 * 16 + ((lane >> 4) << 3) + (lane & 7);
                int cc = kb + ((lane >> 3) & 1);
                uint32_t bd = sw_addr(base + 16384, rr, cc);
                uint32_t t[4];
                LDSM4(t, bd);
                bh[p2 * 2][0] = t[0]; bh[p2 * 2][1] = t[1];
                bh[p2 * 2 + 1][0] = t[2]; bh[p2 * 2 + 1][1] = t[3];
                LDSM4(t, bd + 8192);
                bl[p2 * 2][0] = t[0]; bl[p2 * 2][1] = t[1];
                bl[p2 * 2 + 1][0] = t[2]; bl[p2 * 2 + 1][1] = t[3];
            }
            int arow = (lane & 15);
            int acol = kb + (lane >> 4);
            uint32_t ah[4][4];
#pragma unroll
            for (int mf = 0; mf < 4; mf++)
                LDSM4(ah[mf], sw_addr(base, wm + mf * 16 + arow, acol));
#pragma unroll
            for (int mf = 0; mf < 4; mf++)
#pragma unroll
                for (int nf = 0; nf < 4; nf++) MMA16816(acc[mf][nf], ah[mf], bh[nf]);
#pragma unroll
            for (int mf = 0; mf < 4; mf++)
#pragma unroll
                for (int nf = 0; nf < 4; nf++) MMA16816(acc[mf][nf], ah[mf], bl[nf]);
            uint32_t al[4][4];
#pragma unroll
            for (int mf = 0; mf < 4; mf++)
                LDSM4(al[mf], sw_addr(base + 8192, wm + mf * 16 + arow, acol));
#pragma unroll
            for (int mf = 0; mf < 4; mf++)
#pragma unroll
                for (int nf = 0; nf < 4; nf++) MMA16816(acc[mf][nf], al[mf], bh[nf]);
        }
        if (++stage == 3) stage = 0;
    }

    // epilogue
#pragma unroll
    for (int mf = 0; mf < 4; mf++) {
        int r0 = bm + wm + mf * 16 + (lane >> 2);
        int r1 = r0 + 8;
        int p0 = r0, p1 = r1;
        if (flipC) {
            p0 = (r0 & ~(SEQL - 1)) + (SEQL - 1 - (r0 & (SEQL - 1)));
            p1 = (r1 & ~(SEQL - 1)) + (SEQL - 1 - (r1 & (SEQL - 1)));
        }
#pragma unroll
        for (int nf = 0; nf < 4; nf++) {
            int col = bn + wn + nf * 8 + (lane & 3) * 2;
            if (col >= Ntot) continue;
            float v[4] = {acc[mf][nf][0], acc[mf][nf][1], acc[mf][nf][2], acc[mf][nf][3]};
            if (bias) {
                float b0 = bias[col], b1 = bias[col + 1];
                v[0] += b0; v[1] += b1; v[2] += b0; v[3] += b1;
            }
            if (resid) {
                float2 q0 = *reinterpret_cast<const float2*>(resid + (size_t)p0 * ldc + col);
                float2 q1 = *reinterpret_cast<const float2*>(resid + (size_t)p1 * ldc + col);
                v[0] += q0.x; v[1] += q0.y; v[2] += q1.x; v[3] += q1.y;
            }
            if (Chi) {
                __nv_bfloat16 h0, l0, h1, l1;
                hilo(v[0], h0, l0); hilo(v[1], h1, l1);
                *reinterpret_cast<__nv_bfloat162*>(Chi + (size_t)p0 * ldc + col) =
                    __nv_bfloat162(h0, h1);
                *reinterpret_cast<__nv_bfloat162*>(Clo + (size_t)p0 * ldc + col) =
                    __nv_bfloat162(l0, l1);
                hilo(v[2], h0, l0); hilo(v[3], h1, l1);
                *reinterpret_cast<__nv_bfloat162*>(Chi + (size_t)p1 * ldc + col) =
                    __nv_bfloat162(h0, h1);
                *reinterpret_cast<__nv_bfloat162*>(Clo + (size_t)p1 * ldc + col) =
                    __nv_bfloat162(l0, l1);
            } else {
                *reinterpret_cast<float2*>(C + (size_t)p0 * ldc + col) = make_float2(v[0], v[1]);
                *reinterpret_cast<float2*>(C + (size_t)p1 * ldc + col) = make_float2(v[2], v[3]);
            }
        }
    }
}

// ---------------- rmsnorm -> bf16 hi/lo directly ----------------
__global__ void k_rmsnorm(const float* __restrict__ x, const float* __restrict__ w) {
    int row = blockIdx.x;
    const float* xr = x + (size_t)row * DM;
    float ss = 0.f;
    for (int i = threadIdx.x; i < DM; i += 256) { float v = xr[i]; ss += v * v; }
    __shared__ float sred[8];
    for (int o = 16; o > 0; o >>= 1) ss += __shfl_xor_sync(0xffffffffu, ss, o);
    if ((threadIdx.x & 31) == 0) sred[threadIdx.x >> 5] = ss;
    __syncthreads();
    if (threadIdx.x == 0) {
        float t = 0.f;
        for (int i = 0; i < 8; i++) t += sred[i];
        sred[0] = t;
    }
    __syncthreads();
    float scale = rsqrtf(sred[0] / (float)DM + EPSV);
    for (int i = threadIdx.x; i < DM; i += 256) {
        float v = xr[i] * scale * w[i];
        __nv_bfloat16 h, l; hilo(v, h, l);
        g_XNhi[(size_t)row * DM + i] = h;
        g_XNlo[(size_t)row * DM + i] = l;
    }
}

// ---------------- fused conv + acs (fast-math exp) ----------------
#define CONV_BLOCKS ((ROWS*CONVCH)/256)   // 36864 exact

__global__ void k_conv_acs(const float* __restrict__ zx, float* __restrict__ xBC,
                           const float* __restrict__ conv_w, const float* __restrict__ conv_b,
                           const float* __restrict__ dt_bias, const float* __restrict__ A_log,
                           float* __restrict__ dt, float* __restrict__ Acs) {
    int tid = threadIdx.x;
    if (blockIdx.x < CONV_BLOCKS) {
        int idx = blockIdx.x * 256 + tid;
        int ch = idx % CONVCH;
        int r = idx / CONVCH;
        int l = r & (SEQL - 1);
        float acc = conv_b[ch];
#pragma unroll
        for (int k = 0; k < 4; k++) {
            int ll = l - 3 + k;
            if (ll >= 0)
                acc += zx[(size_t)(r - 3 + k) * DPROJ + DIN + ch] * conv_w[ch * 4 + k];
        }
        xBC[idx] = acc / (1.f + __expf(-acc));
    } else {
        int bb = blockIdx.x - CONV_BLOCKS;
        int c = bb % NCHUNK;
        int h = (bb / NCHUNK) % NH;
        int b = bb / (NCHUNK * NH);
        int l = tid;
        __shared__ float wsum[4];
        float x = 0.f;
        if (l < 128) {
            int row = b * SEQL + c * CH + l;
            float v = zx[(size_t)row * DPROJ + DIN + CONVCH + h] + dt_bias[h];
            float dtv = (v > 20.f) ? v : log1pf(__expf(v));
            dt[row * NH + h] = dtv;
            float Aneg = -__expf(A_log[h]);
            x = Aneg * dtv;
            for (int o = 1; o < 32; o <<= 1) {
                float t = __shfl_up_sync(0xffffffffu, x, o);
                if ((l & 31) >= o) x += t;
            }
            if ((l & 31) == 31) wsum[l >> 5] = x;
        }
        __syncthreads();
        if (l < 128) {
            float add = 0.f;
            int w = l >> 5;
            for (int i = 0; i < w; i++) add += wsum[i];
            Acs[(b * NH + h) * SEQL + c * CH + l] = x + add;
        }
    }
}

// ---------------- fused states + cb ----------------
#define CB_BLOCKS (BATCH*NCHUNK)   // 32

__global__ void __launch_bounds__(256) k_states_cb(
    const float* __restrict__ xBC, const float* __restrict__ dt,
    const float* __restrict__ Acs, float* __restrict__ states,
    float* __restrict__ S) {
    __shared__ float smu[2 * 32 * 132];
    int tid = threadIdx.x;
    int tx = tid & 15, ty = tid >> 4;

    if (blockIdx.x < CB_BLOCKS) {
        int c = blockIdx.x % NCHUNK, b = blockIdx.x / NCHUNK;
        float (*sC)[132]  = reinterpret_cast<float(*)[132]>(smu);
        float (*sBm)[132] = reinterpret_cast<float(*)[132]>(smu + 32 * 132);
        float acc[8][8];
#pragma unroll
        for (int i = 0; i < 8; i++)
#pragma unroll
            for (int j = 0; j < 8; j++) acc[i][j] = 0.f;

        for (int k0 = 0; k0 < DSTATE; k0 += 32) {
            for (int i = tid; i < 32 * 128; i += 256) {
                int kk = i & 31, l = i >> 5;
                int row = b * SEQL + c * CH + l;
                sC[kk][l]  = xBC[(size_t)row * CONVCH + DIN + DSTATE + k0 + kk];
                sBm[kk][l] = xBC[(size_t)row * CONVCH + DIN + k0 + kk];
            }
            __syncthreads();
#pragma unroll
            for (int kk = 0; kk < 32; kk++) {
                float a[8], bv[8];
#pragma unroll
                for (int i = 0; i < 8; i++) a[i] = sC[kk][ty * 8 + i];
#pragma unroll
                for (int j = 0; j < 8; j++) bv[j] = sBm[kk][tx * 8 + j];
#pragma unroll
                for (int i = 0; i < 8; i++)
#pragma unroll
                    for (int j = 0; j < 8; j++) acc[i][j] += a[i] * bv[j];
            }
            __syncthreads();
        }
        size_t base = (size_t)(b * NCHUNK + c) * CH * CH;
#pragma unroll
        for (int i = 0; i < 8; i++)
#pragma unroll
            for (int j = 0; j < 8; j++)
                S[base + (ty * 8 + i) * CH + tx * 8 + j] = acc[i][j];
    } else {
        int bb = blockIdx.x - CB_BLOCKS;
        int h = bb % NH;
        int c = (bb / NH) % NCHUNK;
        int b = bb / (NH * NCHUNK);
        float (*sX)[64]  = reinterpret_cast<float(*)[64]>(smu);
        float (*sB)[132] = reinterpret_cast<float(*)[132]>(smu + 32 * 64);
        float acc[4][8];
#pragma unroll
        for (int i = 0; i < 4; i++)
#pragma unroll
            for (int j = 0; j < 8; j++) acc[i][j] = 0.f;

        const float* AcsRow = Acs + (b * NH + h) * SEQL + c * CH;
        float AcsLast = AcsRow[127];

        for (int lt = 0; lt < 4; lt++) {
            for (int i = tid; i < 32 * 64; i += 256) {
                int l = i >> 6, p = i & 63;
                int row = b * SEQL + c * CH + lt * 32 + l;
                float w = dt[row * NH + h] * __expf(AcsLast - AcsRow[lt * 32 + l]);
                sX[l][p] = xBC[(size_t)row * CONVCH + h * HD + p] * w;
            }
            for (int i = tid; i < 32 * 128; i += 256) {
                int l = i >> 7, n = i & 127;
                int row = b * SEQL + c * CH + lt * 32 + l;
                sB[l][n] = xBC[(size_t)row * CONVCH + DIN + n];
            }
            __syncthreads();
#pragma unroll
            for (int l = 0; l < 32; l++) {
                float xv[4], bv[8];
#pragma unroll
                for (int i = 0; i < 4; i++) xv[i] = sX[l][ty * 4 + i];
#pragma unroll
                for (int j = 0; j < 8; j++) bv[j] = sB[l][tx * 8 + j];
#pragma unroll
                for (int i = 0; i < 4; i++)
#pragma unroll
                    for (int j = 0; j < 8; j++) acc[i][j] += xv[i] * bv[j];
            }
            __syncthreads();
        }
        size_t base = ((size_t)(b * NCHUNK + c) * NH + h) * HD * DSTATE;
#pragma unroll
        for (int i = 0; i < 4; i++)
#pragma unroll
            for (int j = 0; j < 8; j++)
                states[base + (ty * 4 + i) * DSTATE + tx * 8 + j] = acc[i][j];
    }
}

// ---------------- chunk scan (2048 blocks) ----------------
__global__ void k_scan(const float* __restrict__ Acs, const float* __restrict__ states,
                       float* __restrict__ prev) {
    int seg = blockIdx.x & 31;
    int h = (blockIdx.x >> 5) % NH;
    int b = blockIdx.x / (32 * NH);
    int e = seg * 256 + threadIdx.x;
    float s = 0.f;
    for (int c = 0; c < NCHUNK; c++) {
        float cd = __expf(Acs[(b * NH + h) * SEQL + c * CH + 127]);
        size_t base = ((size_t)(b * NCHUNK + c) * NH + h) * HD * DSTATE;
        prev[base + e] = s;
        s = s * cd + states[base + e];
    }
}

// ---------------- Y = Y_diag + Y_off + xs*D (fast-math exp) ----------------
__global__ void __launch_bounds__(256) k_y(
    const float* __restrict__ xBC, const float* __restrict__ dt,
    const float* __restrict__ Acs, const float* __restrict__ prev,
    const float* __restrict__ S, float* __restrict__ y,
    const float* __restrict__ Dvec) {
    int h = blockIdx.x % NH;
    int c = (blockIdx.x / NH) % NCHUNK;
    int b = blockIdx.x / (NH * NCHUNK);
    __shared__ float sG[128][33];
    __shared__ float sT[32][69];
    __shared__ float sAcs[128];
    int tid = threadIdx.x;
    int pb = tid & 15;
    int lb = tid >> 4;
    if (tid < 128) sAcs[tid] = Acs[(b * NH + h) * SEQL + c * CH + tid];
    __syncthreads();

    float acc[8][4], acc2[8][4];
#pragma unroll
    for (int i = 0; i < 8; i++)
#pragma unroll
        for (int j = 0; j < 4; j++) { acc[i][j] = 0.f; acc2[i][j] = 0.f; }

    size_t Sbase = (size_t)(b * NCHUNK + c) * CH * CH;
    for (int st = 0; st < 4; st++) {
        for (int i = tid; i < 128 * 32; i += 256) {
            int s = i & 31, l = i >> 5;
            int sg = st * 32 + s;
            float v = 0.f;
            if (sg <= l) v = S[Sbase + l * CH + sg] * __expf(sAcs[l] - sAcs[sg]);
            sG[l][s] = v;
        }
        for (int i = tid; i < 32 * 64; i += 256) {
            int p = i & 63, s = i >> 6;
            int row = b * SEQL + c * CH + st * 32 + s;
            sT[s][p] = xBC[(size_t)row * CONVCH + h * HD + p] * dt[row * NH + h];
        }
        __syncthreads();
#pragma unroll
        for (int s = 0; s < 32; s++) {
            float gv[8], xv[4];
#pragma unroll
            for (int i = 0; i < 8; i++) gv[i] = sG[lb * 8 + i][s];
#pragma unroll
            for (int j = 0; j < 4; j++) xv[j] = sT[s][pb * 4 + j];
#pragma unroll
            for (int i = 0; i < 8; i++)
#pragma unroll
                for (int j = 0; j < 4; j++) acc[i][j] += gv[i] * xv[j];
        }
        __syncthreads();
    }
    size_t Pbase = ((size_t)(b * NCHUNK + c) * NH + h) * HD * DSTATE;
    for (int nt = 0; nt < 4; nt++) {
        for (int i = tid; i < 128 * 32; i += 256) {
            int n = i & 31, l = i >> 5;
            int row = b * SEQL + c * CH + l;
            sG[l][n] = xBC[(size_t)row * CONVCH + DIN + DSTATE + nt * 32 + n];
        }
        for (int i = tid; i < 32 * 64; i += 256) {
            int n = i & 31, p = i >> 5;
            sT[n][p] = prev[Pbase + p * DSTATE + nt * 32 + n];
        }
        __syncthreads();
#pragma unroll
        for (int n = 0; n < 32; n++) {
            float gv[8], pv[4];
#pragma unroll
            for (int i = 0; i < 8; i++) gv[i] = sG[lb * 8 + i][n];
#pragma unroll
            for (int j = 0; j < 4; j++) pv[j] = sT[n][pb * 4 + j];
#pragma unroll
            for (int i = 0; i < 8; i++)
#pragma unroll
                for (int j = 0; j < 4; j++) acc2[i][j] += gv[i] * pv[j];
        }
        __syncthreads();
    }
    float Dh = Dvec[h];
#pragma unroll
    for (int i = 0; i < 8; i++) {
        int l = lb * 8 + i;
        int row = b * SEQL + c * CH + l;
        float el = __expf(sAcs[l]);
#pragma unroll
        for (int j = 0; j < 4; j++) {
            int p = pb * 4 + j;
            float xsv = xBC[(size_t)row * CONVCH + h * HD + p];
            y[(size_t)row * DIN + h * HD + p] = acc[i][j] + el * acc2[i][j] + xsv * Dh;
        }
    }
}

// ---------------- gated rmsnorm -> bf16 hi/lo directly (fast-math silu) ----------------
__global__ void k_gnorm(const float* __restrict__ zx, const float* __restrict__ y,
                        const float* __restrict__ gnorm_w,
                        __nv_bfloat16* __restrict__ outHi, __nv_bfloat16* __restrict__ outLo) {
    int row = blockIdx.x;
    __shared__ float st[DIN];
    __shared__ float sred[8];
    float ss = 0.f;
    for (int i = threadIdx.x; i < DIN; i += 256) {
        float z = zx[(size_t)row * DPROJ + i];
        float t = y[(size_t)row * DIN + i] * (z / (1.f + __expf(-z)));
        st[i] = t;
        ss += t * t;
    }
    for (int o = 16; o > 0; o >>= 1) ss += __shfl_xor_sync(0xffffffffu, ss, o);
    if ((threadIdx.x & 31) == 0) sred[threadIdx.x >> 5] = ss;
    __syncthreads();
    if (threadIdx.x == 0) {
        float t = 0.f;
        for (int i = 0; i < 8; i++) t += sred[i];
        sred[0] = t;
    }
    __syncthreads();
    float scale = rsqrtf(sred[0] / (float)DIN + EPSV);
    for (int i = threadIdx.x; i < DIN; i += 256) {
        float v = st[i] * scale * gnorm_w[i];
        __nv_bfloat16 h, l; hilo(v, h, l);
        outHi[(size_t)row * DIN + i] = h;
        outLo[(size_t)row * DIN + i] = l;
    }
}

// ---------------- host helpers ----------------
static void cvt(cudaStream_t st, const float* src, __nv_bfloat16* hi, __nv_bfloat16* lo,
                long nvalid, long total) {
    long blocks = (total / 8 + 255) / 256;
    k_cvt<<<(unsigned)blocks, 256, 0, st>>>(src, hi, lo, nvalid, total);
}

static void hgemm(cudaStream_t st,
                  const __nv_bfloat16* Ahi, const __nv_bfloat16* Alo, int lda, int K, int flipA,
                  const __nv_bfloat16* Whi, const __nv_bfloat16* Wlo, int ldw, int Ntot,
                  float* C, __nv_bfloat16* Chi, __nv_bfloat16* Clo, int ldc, int flipC,
                  const float* resid, const float* bias) {
    dim3 grid((Ntot + 127) / 128, ROWS / 128);
    k_hgemm<<<grid, 256, HSMEM, st>>>(Ahi, Alo, lda, K, flipA, Whi, Wlo, ldw, Ntot,
                                      C, Chi, Clo, ldc, flipC, resid, bias);
}

extern "C" void kernel_launch(void* const* d_in, const int* in_sizes, int n_in,
                              void* d_out, int out_size) {
    (void)in_sizes; (void)n_in; (void)out_size;
    const float* x         = (const float*)d_in[0];
    const float* norm_w    = (const float*)d_in[1];
    const float* out_w_blk = (const float*)d_in[2];
    const float* out_b_blk = (const float*)d_in[3];

    static cudaStream_t s2 = nullptr;
    static cudaEvent_t evA = nullptr, evB = nullptr, evC = nullptr;
    if (!s2) {
        cudaStreamCreateWithFlags(&s2, cudaStreamNonBlocking);
        cudaEventCreateWithFlags(&evA, cudaEventDisableTiming);
        cudaEventCreateWithFlags(&evB, cudaEventDisableTiming);
        cudaEventCreateWithFlags(&evC, cudaEventDisableTiming);
        cudaFuncSetAttribute(k_hgemm, cudaFuncAttributeMaxDynamicSharedMemorySize, HSMEM);
    }

    float *p_zx, *p_xBC, *p_dt, *p_Acs, *p_states, *p_prev, *p_S, *p_y;
    __nv_bfloat16 *p_XNhi, *p_XNlo, *p_Ahi, *p_Alo, *p_YChi, *p_YClo, *p_Whi, *p_Wlo;
    __nv_bfloat16 *p_WFhi, *p_WFlo;
    cudaGetSymbolAddress((void**)&p_zx,     g_zx);
    cudaGetSymbolAddress((void**)&p_xBC,    g_xBC);
    cudaGetSymbolAddress((void**)&p_dt,     g_dt);
    cudaGetSymbolAddress((void**)&p_Acs,    g_Acs);
    cudaGetSymbolAddress((void**)&p_states, g_states);
    cudaGetSymbolAddress((void**)&p_prev,   g_prev);
    cudaGetSymbolAddress((void**)&p_S,      g_S);
    cudaGetSymbolAddress((void**)&p_y,      g_y);
    cudaGetSymbolAddress((void**)&p_XNhi,   g_XNhi);
    cudaGetSymbolAddress((void**)&p_XNlo,   g_XNlo);
    cudaGetSymbolAddress((void**)&p_Ahi,    g_Ahi);
    cudaGetSymbolAddress((void**)&p_Alo,    g_Alo);
    cudaGetSymbolAddress((void**)&p_YChi,   g_YChi);
    cudaGetSymbolAddress((void**)&p_YClo,   g_YClo);
    cudaGetSymbolAddress((void**)&p_Whi,    g_Whi);
    cudaGetSymbolAddress((void**)&p_Wlo,    g_Wlo);
    cudaGetSymbolAddress((void**)&p_WFhi,   g_WFhi);
    cudaGetSymbolAddress((void**)&p_WFlo,   g_WFlo);

    k_rmsnorm<<<ROWS, 256, 0, 0>>>(x, norm_w);

    // fork: s2 joins the capture via evA BEFORE any s2 work (capture-legal order)
    cudaEventRecord(evA, 0);
    cudaStreamWaitEvent(s2, evA, 0);

    // WF weight cvt on s2 (after fork), ahead of the dir-1 chain; evC gates partial-final-#1
    cvt(s2, out_w_blk, p_WFhi, p_WFlo, (long)DM * 2 * DM, (long)DM * 2 * DM);
    cudaEventRecord(evC, s2);

    for (int d = 0; d < 2; d++) {
        cudaStream_t st = (d == 0) ? (cudaStream_t)0 : s2;
        const float* in_w    = (const float*)d_in[4 + d * 8 + 0];
        const float* conv_w  = (const float*)d_in[4 + d * 8 + 1];
        const float* conv_b  = (const float*)d_in[4 + d * 8 + 2];
        const float* dt_bias = (const float*)d_in[4 + d * 8 + 3];
        const float* A_log   = (const float*)d_in[4 + d * 8 + 4];
        const float* Dv      = (const float*)d_in[4 + d * 8 + 5];
        const float* gnw     = (const float*)d_in[4 + d * 8 + 6];
        const float* out_w   = (const float*)d_in[4 + d * 8 + 7];

        float* zx     = p_zx     + (size_t)d * ROWS * DPROJ;
        float* xBC    = p_xBC    + (size_t)d * ROWS * CONVCH;
        float* dt     = p_dt     + (size_t)d * ROWS * NH;
        float* Acs    = p_Acs    + (size_t)d * BATCH * NH * SEQL;
        float* states = p_states + (size_t)d * BATCH * NCHUNK * NH * HD * DSTATE;
        float* prev   = p_prev   + (size_t)d * BATCH * NCHUNK * NH * HD * DSTATE;
        float* S      = p_S      + (size_t)d * BATCH * NCHUNK * CH * CH;
        float* y      = p_y      + (size_t)d * ROWS * DIN;
        __nv_bfloat16* Ahi = p_Ahi + (size_t)d * ROWS * DIN;
        __nv_bfloat16* Alo = p_Alo + (size_t)d * ROWS * DIN;
        __nv_bfloat16* Whi = p_Whi + (size_t)d * NPADW * DM;
        __nv_bfloat16* Wlo = p_Wlo + (size_t)d * NPADW * DM;

        cvt(st, in_w, Whi, Wlo, (long)DPROJ * DM, (long)NPADW * DM);
        hgemm(st, p_XNhi, p_XNlo, DM, DM, d, Whi, Wlo, DM, DPROJ,
              zx, nullptr, nullptr, DPROJ, 0, nullptr, nullptr);

        k_conv_acs<<<CONV_BLOCKS + BATCH * NH * NCHUNK, 256, 0, st>>>(
            zx, xBC, conv_w, conv_b, dt_bias, A_log, dt, Acs);
        k_states_cb<<<CB_BLOCKS + BATCH * NCHUNK * NH, 256, 0, st>>>(
            xBC, dt, Acs, states, S);
        k_scan<<<BATCH * NH * 32, 256, 0, st>>>(Acs, states, prev);
        k_y<<<BATCH * NCHUNK * NH, 256, 0, st>>>(xBC, dt, Acs, prev, S, y, Dv);
        k_gnorm<<<ROWS, 256, 0, st>>>(zx, y, gnw, Ahi, Alo);

        cvt(st, out_w, Whi, Wlo, (long)DM * DIN, (long)DM * DIN);
        hgemm(st, Ahi, Alo, DIN, DIN, 0, Whi, Wlo, DIN, DM,
              nullptr, p_YChi + d * DM, p_YClo + d * DM, 2 * DM, d, nullptr, nullptr);
    }

    // partial final GEMM #1 (fwd half) on stream0: overlaps dir-1 tail.
    cudaStreamWaitEvent(0, evC, 0);
    hgemm(0, p_YChi, p_YClo, 2 * DM, DM, 0, p_WFhi, p_WFlo, 2 * DM, DM,
          (float*)d_out, nullptr, nullptr, DM, 0, x, out_b_blk);

    // join with dir-1, then partial #2 (bwd half): out += Y_bwd @ W2^T
    cudaEventRecord(evB, s2);
    cudaStreamWaitEvent(0, evB, 0);
    hgemm(0, p_YChi + DM, p_YClo + DM, 2 * DM, DM, 0, p_WFhi + DM, p_WFlo + DM, 2 * DM, DM,
          (float*)d_out, nullptr, nullptr, DM, 0, (float*)d_out, nullptr);
}

// round 15
// speedup vs baseline: 1.5250x; 1.5250x over previous
#include <cuda_runtime.h>
#include <cuda_bf16.h>
#include <math.h>
#include <stdint.h>

// ---------------- problem constants ----------------
#define BATCH   2
#define SEQL    2048
#define DM      1024
#define DIN     2048      // D_INNER
#define DSTATE  128
#define NH      32
#define HD      64
#define DPROJ   4384      // D_IN_PROJ
#define CONVCH  2304      // D_INNER + 2*D_STATE
#define NCHUNK  16
#define CH      128
#define EPSV    1e-5f
#define ROWS    (BATCH*SEQL)   // 4096
#define NPADW   4480           // 35*128, padded N for widest weight

// ---------------- scratch (device globals; [2] = per direction) ----------------
__device__ float g_zx    [2][ROWS*DPROJ];
__device__ float g_xBC   [2][ROWS*CONVCH];
__device__ float g_dt    [2][ROWS*NH];
__device__ float g_Acs   [2][BATCH*NH*SEQL];
__device__ float g_states[2][BATCH*NCHUNK*NH*HD*DSTATE];
__device__ float g_prev  [2][BATCH*NCHUNK*NH*HD*DSTATE];
__device__ float g_S     [2][BATCH*NCHUNK*CH*CH];
__device__ float g_y     [2][ROWS*DIN];

__device__ __nv_bfloat16 g_XNhi[ROWS*DM];
__device__ __nv_bfloat16 g_XNlo[ROWS*DM];
__device__ __nv_bfloat16 g_Ahi [2][ROWS*DIN];
__device__ __nv_bfloat16 g_Alo [2][ROWS*DIN];
__device__ __nv_bfloat16 g_YChi[ROWS*2*DM];
__device__ __nv_bfloat16 g_YClo[ROWS*2*DM];
__device__ __nv_bfloat16 g_Whi [2][NPADW*DM];
__device__ __nv_bfloat16 g_Wlo [2][NPADW*DM];
__device__ __nv_bfloat16 g_WFhi[2*DM*DM];
__device__ __nv_bfloat16 g_WFlo[2*DM*DM];

// ---------------- asm helpers ----------------
__device__ __forceinline__ uint32_t smem_u32(const void* p) {
    uint32_t a;
    asm("{ .reg .u64 t; cvta.to.shared.u64 t, %1; cvt.u32.u64 %0, t; }" : "=r"(a) : "l"(p));
    return a;
}
#define CP16(d, s) asm volatile("cp.async.cg.shared.global [%0], [%1], 16;" :: "r"(d), "l"(s))
#define CP_COMMIT() asm volatile("cp.async.commit_group;")
#define LDSM4(r, a) asm volatile("ldmatrix.sync.aligned.m8n8.x4.shared.b16 {%0,%1,%2,%3}, [%4];" \
    : "=r"((r)[0]), "=r"((r)[1]), "=r"((r)[2]), "=r"((r)[3]) : "r"(a))
#define MMA16816(d, a, b) asm volatile( \
    "mma.sync.aligned.m16n8k16.row.col.f32.bf16.bf16.f32 " \
    "{%0,%1,%2,%3}, {%4,%5,%6,%7}, {%8,%9}, {%0,%1,%2,%3};" \
    : "+f"((d)[0]), "+f"((d)[1]), "+f"((d)[2]), "+f"((d)[3]) \
    : "r"((a)[0]), "r"((a)[1]), "r"((a)[2]), "r"((a)[3]), "r"((b)[0]), "r"((b)[1]))

__device__ __forceinline__ uint32_t sw_addr(uint32_t base, int row, int chunk) {
    return base + (uint32_t)row * 64u + ((((uint32_t)chunk) ^ (((uint32_t)row >> 1) & 3u)) << 4);
}

__device__ __forceinline__ void hilo(float v, __nv_bfloat16& h, __nv_bfloat16& l) {
    h = __float2bfloat16(v);
    l = __float2bfloat16(v - __bfloat162float(h));
}

// ---------------- fp32 -> bf16 hi/lo conversion (weights; with zero padding) ----------------
__global__ void k_cvt(const float* __restrict__ src, __nv_bfloat16* __restrict__ hi,
                      __nv_bfloat16* __restrict__ lo, long nvalid, long total) {
    long idx = ((long)blockIdx.x * 256 + threadIdx.x) * 8;
    if (idx >= total) return;
    uint4 hq = make_uint4(0, 0, 0, 0), lq = make_uint4(0, 0, 0, 0);
    if (idx < nvalid) {
        float4 f0 = *reinterpret_cast<const float4*>(src + idx);
        float4 f1 = *reinterpret_cast<const float4*>(src + idx + 4);
        float f[8] = {f0.x, f0.y, f0.z, f0.w, f1.x, f1.y, f1.z, f1.w};
        uint32_t h[8], l[8];
#pragma unroll
        for (int i = 0; i < 8; i++) {
            __nv_bfloat16 hb, lb; hilo(f[i], hb, lb);
            h[i] = __bfloat16_as_ushort(hb);
            l[i] = __bfloat16_as_ushort(lb);
        }
        hq.x = (h[1] << 16) | h[0]; hq.y = (h[3] << 16) | h[2];
        hq.z = (h[5] << 16) | h[4]; hq.w = (h[7] << 16) | h[6];
        lq.x = (l[1] << 16) | l[0]; lq.y = (l[3] << 16) | l[2];
        lq.z = (l[5] << 16) | l[4]; lq.w = (l[7] << 16) | l[6];
    }
    *reinterpret_cast<uint4*>(hi + idx) = hq;
    *reinterpret_cast<uint4*>(lo + idx) = lq;
}

// ---------------- HMMA GEMM (3-stage cp.async pipeline; batched A-frag loads) ----------------
#define HSMEM 98304

__global__ void __launch_bounds__(256, 2) k_hgemm(
    const __nv_bfloat16* __restrict__ Ahi, const __nv_bfloat16* __restrict__ Alo,
    int lda, int K, int flipA,
    const __nv_bfloat16* __restrict__ Whi, const __nv_bfloat16* __restrict__ Wlo,
    int ldw, int Ntot, float* __restrict__ C,
    __nv_bfloat16* __restrict__ Chi, __nv_bfloat16* __restrict__ Clo,
    int ldc, int flipC,
    const float* __restrict__ resid, const float* __restrict__ bias)
{
    extern __shared__ char smraw[];
    const uint32_t sb = smem_u32(smraw);
    const int tid = threadIdx.x, lane = tid & 31, wid = tid >> 5;
    const int bm = blockIdx.y * 128, bn = blockIdx.x * 128;
    const int wm = (wid & 1) * 64, wn = (wid >> 1) * 32;

    float acc[4][4][4];
#pragma unroll
    for (int i = 0; i < 4; i++)
#pragma unroll
        for (int j = 0; j < 4; j++)
#pragma unroll
            for (int k = 0; k < 4; k++) acc[i][j][k] = 0.f;

    const int ktiles = K / 32;

    auto load_stage = [&](int s, int k0) {
        uint32_t base = sb + s * 32768;
#pragma unroll
        for (int it = 0; it < 2; it++) {
            int q = tid + it * 256;
            int r = q >> 2, c = q & 3;
            int gr = bm + r, pr = gr;
            if (flipA) pr = (gr & ~(SEQL - 1)) + (SEQL - 1 - (gr & (SEQL - 1)));
            uint32_t d = sw_addr(base, r, c);
            size_t aoff = (size_t)pr * lda + k0 + c * 8;
            CP16(d,         (const char*)(Ahi + aoff));
            CP16(d + 8192,  (const char*)(Alo + aoff));
            size_t woff = (size_t)(bn + r) * ldw + k0 + c * 8;
            CP16(d + 16384, (const char*)(Whi + woff));
            CP16(d + 24576, (const char*)(Wlo + woff));
        }
        CP_COMMIT();
    };

    load_stage(0, 0);
    load_stage(1, 32);

    int stage = 0;
    for (int i = 0; i < ktiles; i++) {
        if (i == ktiles - 1) {
            asm volatile("cp.async.wait_group 0;");
        } else {
            asm volatile("cp.async.wait_group 1;");
        }
        __syncthreads();
        if (i + 2 < ktiles) {
            int ns = stage + 2; if (ns >= 3) ns -= 3;
            load_stage(ns, (i + 2) * 32);
        }
        uint32_t base = sb + stage * 32768;
#pragma unroll
        for (int ks = 0; ks < 2; ks++) {
            const int kb = ks * 2;
            uint32_t bh[4][2], bl[4][2];
#pragma unroll
            for (int p2 = 0; p2 < 2; p2++) {
                int rr = wn + p2 * 16 + ((lane >> 4) << 3) + (lane & 7);
                int cc = kb + ((lane >> 3) & 1);
                uint32_t bd = sw_addr(base + 16384, rr, cc);
                uint32_t t[4];
                LDSM4(t, bd);
                bh[p2 * 2][0] = t[0]; bh[p2 * 2][1] = t[1];
                bh[p2 * 2 + 1][0] = t[2]; bh[p2 * 2 + 1][1] = t[3];
                LDSM4(t, bd + 8192);
                bl[p2 * 2][0] = t[0]; bl[p2 * 2][1] = t[1];
                bl[p2 * 2 + 1][0] = t[2]; bl[p2 * 2 + 1][1] = t[3];
            }
            int arow = (lane & 15);
            int acol = kb + (lane >> 4);
            uint32_t ah[4][4];
#pragma unroll
            for (int mf = 0; mf < 4; mf++)
                LDSM4(ah[mf], sw_addr(base, wm + mf * 16 + arow, acol));
#pragma unroll
            for (int mf = 0; mf < 4; mf++)
#pragma unroll
                for (int nf = 0; nf < 4; nf++) MMA16816(acc[mf][nf], ah[mf], bh[nf]);
#pragma unroll
            for (int mf = 0; mf < 4; mf++)
#pragma unroll
                for (int nf = 0; nf < 4; nf++) MMA16816(acc[mf][nf], ah[mf], bl[nf]);
            uint32_t al[4][4];
#pragma unroll
            for (int mf = 0; mf < 4; mf++)
                LDSM4(al[mf], sw_addr(base + 8192, wm + mf * 16 + arow, acol));
#pragma unroll
            for (int mf = 0; mf < 4; mf++)
#pragma unroll
                for (int nf = 0; nf < 4; nf++) MMA16816(acc[mf][nf], al[mf], bh[nf]);
        }
        if (++stage == 3) stage = 0;
    }

    // epilogue
#pragma unroll
    for (int mf = 0; mf < 4; mf++) {
        int r0 = bm + wm + mf * 16 + (lane >> 2);
        int r1 = r0 + 8;
        int p0 = r0, p1 = r1;
        if (flipC) {
            p0 = (r0 & ~(SEQL - 1)) + (SEQL - 1 - (r0 & (SEQL - 1)));
            p1 = (r1 & ~(SEQL - 1)) + (SEQL - 1 - (r1 & (SEQL - 1)));
        }
#pragma unroll
        for (int nf = 0; nf < 4; nf++) {
            int col = bn + wn + nf * 8 + (lane & 3) * 2;
            if (col >= Ntot) continue;
            float v[4] = {acc[mf][nf][0], acc[mf][nf][1], acc[mf][nf][2], acc[mf][nf][3]};
            if (bias) {
                float b0 = bias[col], b1 = bias[col + 1];
                v[0] += b0; v[1] += b1; v[2] += b0; v[3] += b1;
            }
            if (resid) {
                float2 q0 = *reinterpret_cast<const float2*>(resid + (size_t)p0 * ldc + col);
                float2 q1 = *reinterpret_cast<const float2*>(resid + (size_t)p1 * ldc + col);
                v[0] += q0.x; v[1] += q0.y; v[2] += q1.x; v[3] += q1.y;
            }
            if (Chi) {
                __nv_bfloat16 h0, l0, h1, l1;
                hilo(v[0], h0, l0); hilo(v[1], h1, l1);
                *reinterpret_cast<__nv_bfloat162*>(Chi + (size_t)p0 * ldc + col) =
                    __nv_bfloat162(h0, h1);
                *reinterpret_cast<__nv_bfloat162*>(Clo + (size_t)p0 * ldc + col) =
                    __nv_bfloat162(l0, l1);
                hilo(v[2], h0, l0); hilo(v[3], h1, l1);
                *reinterpret_cast<__nv_bfloat162*>(Chi + (size_t)p1 * ldc + col) =
                    __nv_bfloat162(h0, h1);
                *reinterpret_cast<__nv_bfloat162*>(Clo + (size_t)p1 * ldc + col) =
                    __nv_bfloat162(l0, l1);
            } else {
                *reinterpret_cast<float2*>(C + (size_t)p0 * ldc + col) = make_float2(v[0], v[1]);
                *reinterpret_cast<float2*>(C + (size_t)p1 * ldc + col) = make_float2(v[2], v[3]);
            }
        }
    }
}

// ---------------- rmsnorm -> bf16 hi/lo directly ----------------
__global__ void k_rmsnorm(const float* __restrict__ x, const float* __restrict__ w) {
    int row = blockIdx.x;
    const float* xr = x + (size_t)row * DM;
    float ss = 0.f;
    for (int i = threadIdx.x; i < DM; i += 256) { float v = xr[i]; ss += v * v; }
    __shared__ float sred[8];
    for (int o = 16; o > 0; o >>= 1) ss += __shfl_xor_sync(0xffffffffu, ss, o);
    if ((threadIdx.x & 31) == 0) sred[threadIdx.x >> 5] = ss;
    __syncthreads();
    if (threadIdx.x == 0) {
        float t = 0.f;
        for (int i = 0; i < 8; i++) t += sred[i];
        sred[0] = t;
    }
    __syncthreads();
    float scale = rsqrtf(sred[0] / (float)DM + EPSV);
    for (int i = threadIdx.x; i < DM; i += 256) {
        float v = xr[i] * scale * w[i];
        __nv_bfloat16 h, l; hilo(v, h, l);
        g_XNhi[(size_t)row * DM + i] = h;
        g_XNlo[(size_t)row * DM + i] = l;
    }
}

// ---------------- fused conv + acs (fast-math exp) ----------------
#define CONV_BLOCKS ((ROWS*CONVCH)/256)   // 36864 exact

__global__ void k_conv_acs(const float* __restrict__ zx, float* __restrict__ xBC,
                           const float* __restrict__ conv_w, const float* __restrict__ conv_b,
                           const float* __restrict__ dt_bias, const float* __restrict__ A_log,
                           float* __restrict__ dt, float* __restrict__ Acs) {
    int tid = threadIdx.x;
    if (blockIdx.x < CONV_BLOCKS) {
        int idx = blockIdx.x * 256 + tid;
        int ch = idx % CONVCH;
        int r = idx / CONVCH;
        int l = r & (SEQL - 1);
        float acc = conv_b[ch];
#pragma unroll
        for (int k = 0; k < 4; k++) {
            int ll = l - 3 + k;
            if (ll >= 0)
                acc += zx[(size_t)(r - 3 + k) * DPROJ + DIN + ch] * conv_w[ch * 4 + k];
        }
        xBC[idx] = acc / (1.f + __expf(-acc));
    } else {
        int bb = blockIdx.x - CONV_BLOCKS;
        int c = bb % NCHUNK;
        int h = (bb / NCHUNK) % NH;
        int b = bb / (NCHUNK * NH);
        int l = tid;
        __shared__ float wsum[4];
        float x = 0.f;
        if (l < 128) {
            int row = b * SEQL + c * CH + l;
            float v = zx[(size_t)row * DPROJ + DIN + CONVCH + h] + dt_bias[h];
            float dtv = (v > 20.f) ? v : log1pf(__expf(v));
            dt[row * NH + h] = dtv;
            float Aneg = -__expf(A_log[h]);
            x = Aneg * dtv;
            for (int o = 1; o < 32; o <<= 1) {
                float t = __shfl_up_sync(0xffffffffu, x, o);
                if ((l & 31) >= o) x += t;
            }
            if ((l & 31) == 31) wsum[l >> 5] = x;
        }
        __syncthreads();
        if (l < 128) {
            float add = 0.f;
            int w = l >> 5;
            for (int i = 0; i < w; i++) add += wsum[i];
            Acs[(b * NH + h) * SEQL + c * CH + l] = x + add;
        }
    }
}

// ---------------- fused states + cb ----------------
#define CB_BLOCKS (BATCH*NCHUNK)   // 32

__global__ void __launch_bounds__(256) k_states_cb(
    const float* __restrict__ xBC, const float* __restrict__ dt,
    const float* __restrict__ Acs, float* __restrict__ states,
    float* __restrict__ S) {
    __shared__ float smu[2 * 32 * 132];
    int tid = threadIdx.x;
    int tx = tid & 15, ty = tid >> 4;

    if (blockIdx.x < CB_BLOCKS) {
        int c = blockIdx.x % NCHUNK, b = blockIdx.x / NCHUNK;
        float (*sC)[132]  = reinterpret_cast<float(*)[132]>(smu);
        float (*sBm)[132] = reinterpret_cast<float(*)[132]>(smu + 32 * 132);
        float acc[8][8];
#pragma unroll
        for (int i = 0; i < 8; i++)
#pragma unroll
            for (int j = 0; j < 8; j++) acc[i][j] = 0.f;

        for (int k0 = 0; k0 < DSTATE; k0 += 32) {
            for (int i = tid; i < 32 * 128; i += 256) {
                int kk = i & 31, l = i >> 5;
                int row = b * SEQL + c * CH + l;
                sC[kk][l]  = xBC[(size_t)row * CONVCH + DIN + DSTATE + k0 + kk];
                sBm[kk][l] = xBC[(size_t)row * CONVCH + DIN + k0 + kk];
            }
            __syncthreads();
#pragma unroll
            for (int kk = 0; kk < 32; kk++) {
                float a[8], bv[8];
#pragma unroll
                for (int i = 0; i < 8; i++) a[i] = sC[kk][ty * 8 + i];
#pragma unroll
                for (int j = 0; j < 8; j++) bv[j] = sBm[kk][tx * 8 + j];
#pragma unroll
                for (int i = 0; i < 8; i++)
#pragma unroll
                    for (int j = 0; j < 8; j++) acc[i][j] += a[i] * bv[j];
            }
            __syncthreads();
        }
        size_t base = (size_t)(b * NCHUNK + c) * CH * CH;
#pragma unroll
        for (int i = 0; i < 8; i++)
#pragma unroll
            for (int j = 0; j < 8; j++)
                S[base + (ty * 8 + i) * CH + tx * 8 + j] = acc[i][j];
    } else {
        int bb = blockIdx.x - CB_BLOCKS;
        int h = bb % NH;
        int c = (bb / NH) % NCHUNK;
        int b = bb / (NH * NCHUNK);
        float (*sX)[64]  = reinterpret_cast<float(*)[64]>(smu);
        float (*sB)[132] = reinterpret_cast<float(*)[132]>(smu + 32 * 64);
        float acc[4][8];
#pragma unroll
        for (int i = 0; i < 4; i++)
#pragma unroll
            for (int j = 0; j < 8; j++) acc[i][j] = 0.f;

        const float* AcsRow = Acs + (b * NH + h) * SEQL + c * CH;
        float AcsLast = AcsRow[127];

        for (int lt = 0; lt < 4; lt++) {
            for (int i = tid; i < 32 * 64; i += 256) {
                int l = i >> 6, p = i & 63;
                int row = b * SEQL + c * CH + lt * 32 + l;
                float w = dt[row * NH + h] * __expf(AcsLast - AcsRow[lt * 32 + l]);
                sX[l][p] = xBC[(size_t)row * CONVCH + h * HD + p] * w;
            }
            for (int i = tid; i < 32 * 128; i += 256) {
                int l = i >> 7, n = i & 127;
                int row = b * SEQL + c * CH + lt * 32 + l;
                sB[l][n] = xBC[(size_t)row * CONVCH + DIN + n];
            }
            __syncthreads();
#pragma unroll
            for (int l = 0; l < 32; l++) {
                float xv[4], bv[8];
#pragma unroll
                for (int i = 0; i < 4; i++) xv[i] = sX[l][ty * 4 + i];
#pragma unroll
                for (int j = 0; j < 8; j++) bv[j] = sB[l][tx * 8 + j];
#pragma unroll
                for (int i = 0; i < 4; i++)
#pragma unroll
                    for (int j = 0; j < 8; j++) acc[i][j] += xv[i] * bv[j];
            }
            __syncthreads();
        }
        size_t base = ((size_t)(b * NCHUNK + c) * NH + h) * HD * DSTATE;
#pragma unroll
        for (int i = 0; i < 4; i++)
#pragma unroll
            for (int j = 0; j < 8; j++)
                states[base + (ty * 4 + i) * DSTATE + tx * 8 + j] = acc[i][j];
    }
}

// ---------------- chunk scan (2048 blocks) ----------------
__global__ void k_scan(const float* __restrict__ Acs, const float* __restrict__ states,
                       float* __restrict__ prev) {
    int seg = blockIdx.x & 31;
    int h = (blockIdx.x >> 5) % NH;
    int b = blockIdx.x / (32 * NH);
    int e = seg * 256 + threadIdx.x;
    float s = 0.f;
    for (int c = 0; c < NCHUNK; c++) {
        float cd = __expf(Acs[(b * NH + h) * SEQL + c * CH + 127]);
        size_t base = ((size_t)(b * NCHUNK + c) * NH + h) * HD * DSTATE;
        prev[base + e] = s;
        s = s * cd + states[base + e];
    }
}

// ---------------- Y = Y_diag + Y_off + xs*D (fast-math exp) ----------------
__global__ void __launch_bounds__(256) k_y(
    const float* __restrict__ xBC, const float* __restrict__ dt,
    const float* __restrict__ Acs, const float* __restrict__ prev,
    const float* __restrict__ S, float* __restrict__ y,
    const float* __restrict__ Dvec) {
    int h = blockIdx.x % NH;
    int c = (blockIdx.x / NH) % NCHUNK;
    int b = blockIdx.x / (NH * NCHUNK);
    __shared__ float sG[128][33];
    __shared__ float sT[32][69];
    __shared__ float sAcs[128];
    int tid = threadIdx.x;
    int pb = tid & 15;
    int lb = tid >> 4;
    if (tid < 128) sAcs[tid] = Acs[(b * NH + h) * SEQL + c * CH + tid];
    __syncthreads();

    float acc[8][4], acc2[8][4];
#pragma unroll
    for (int i = 0; i < 8; i++)
#pragma unroll
        for (int j = 0; j < 4; j++) { acc[i][j] = 0.f; acc2[i][j] = 0.f; }

    size_t Sbase = (size_t)(b * NCHUNK + c) * CH * CH;
    for (int st = 0; st < 4; st++) {
        for (int i = tid; i < 128 * 32; i += 256) {
            int s = i & 31, l = i >> 5;
            int sg = st * 32 + s;
            float v = 0.f;
            if (sg <= l) v = S[Sbase + l * CH + sg] * __expf(sAcs[l] - sAcs[sg]);
            sG[l][s] = v;
        }
        for (int i = tid; i < 32 * 64; i += 256) {
            int p = i & 63, s = i >> 6;
            int row = b * SEQL + c * CH + st * 32 + s;
            sT[s][p] = xBC[(size_t)row * CONVCH + h * HD + p] * dt[row * NH + h];
        }
        __syncthreads();
#pragma unroll
        for (int s = 0; s < 32; s++) {
            float gv[8], xv[4];
#pragma unroll
            for (int i = 0; i < 8; i++) gv[i] = sG[lb * 8 + i][s];
#pragma unroll
            for (int j = 0; j < 4; j++) xv[j] = sT[s][pb * 4 + j];
#pragma unroll
            for (int i = 0; i < 8; i++)
#pragma unroll
                for (int j = 0; j < 4; j++) acc[i][j] += gv[i] * xv[j];
        }
        __syncthreads();
    }
    size_t Pbase = ((size_t)(b * NCHUNK + c) * NH + h) * HD * DSTATE;
    for (int nt = 0; nt < 4; nt++) {
        for (int i = tid; i < 128 * 32; i += 256) {
            int n = i & 31, l = i >> 5;
            int row = b * SEQL + c * CH + l;
            sG[l][n] = xBC[(size_t)row * CONVCH + DIN + DSTATE + nt * 32 + n];
        }
        for (int i = tid; i < 32 * 64; i += 256) {
            int n = i & 31, p = i >> 5;
            sT[n][p] = prev[Pbase + p * DSTATE + nt * 32 + n];
        }
        __syncthreads();
#pragma unroll
        for (int n = 0; n < 32; n++) {
            float gv[8], pv[4];
#pragma unroll
            for (int i = 0; i < 8; i++) gv[i] = sG[lb * 8 + i][n];
#pragma unroll
            for (int j = 0; j < 4; j++) pv[j] = sT[n][pb * 4 + j];
#pragma unroll
            for (int i = 0; i < 8; i++)
#pragma unroll
                for (int j = 0; j < 4; j++) acc2[i][j] += gv[i] * pv[j];
        }
        __syncthreads();
    }
    float Dh = Dvec[h];
#pragma unroll
    for (int i = 0; i < 8; i++) {
        int l = lb * 8 + i;
        int row = b * SEQL + c * CH + l;
        float el = __expf(sAcs[l]);
#pragma unroll
        for (int j = 0; j < 4; j++) {
            int p = pb * 4 + j;
            float xsv = xBC[(size_t)row * CONVCH + h * HD + p];
            y[(size_t)row * DIN + h * HD + p] = acc[i][j] + el * acc2[i][j] + xsv * Dh;
        }
    }
}

// ---------------- gated rmsnorm -> bf16 hi/lo directly (fast-math silu) ----------------
__global__ void k_gnorm(const float* __restrict__ zx, const float* __restrict__ y,
                        const float* __restrict__ gnorm_w,
                        __nv_bfloat16* __restrict__ outHi, __nv_bfloat16* __restrict__ outLo) {
    int row = blockIdx.x;
    __shared__ float st[DIN];
    __shared__ float sred[8];
    float ss = 0.f;
    for (int i = threadIdx.x; i < DIN; i += 256) {
        float z = zx[(size_t)row * DPROJ + i];
        float t = y[(size_t)row * DIN + i] * (z / (1.f + __expf(-z)));
        st[i] = t;
        ss += t * t;
    }
    for (int o = 16; o > 0; o >>= 1) ss += __shfl_xor_sync(0xffffffffu, ss, o);
    if ((threadIdx.x & 31) == 0) sred[threadIdx.x >> 5] = ss;
    __syncthreads();
    if (threadIdx.x == 0) {
        float t = 0.f;
        for (int i = 0; i < 8; i++) t += sred[i];
        sred[0] = t;
    }
    __syncthreads();
    float scale = rsqrtf(sred[0] / (float)DIN + EPSV);
    for (int i = threadIdx.x; i < DIN; i += 256) {
        float v = st[i] * scale * gnorm_w[i];
        __nv_bfloat16 h, l; hilo(v, h, l);
        outHi[(size_t)row * DIN + i] = h;
        outLo[(size_t)row * DIN + i] = l;
    }
}

// ---------------- host helpers ----------------
static void cvt(cudaStream_t st, const float* src, __nv_bfloat16* hi, __nv_bfloat16* lo,
                long nvalid, long total) {
    long blocks = (total / 8 + 255) / 256;
    k_cvt<<<(unsigned)blocks, 256, 0, st>>>(src, hi, lo, nvalid, total);
}

static void hgemm(cudaStream_t st,
                  const __nv_bfloat16* Ahi, const __nv_bfloat16* Alo, int lda, int K, int flipA,
                  const __nv_bfloat16* Whi, const __nv_bfloat16* Wlo, int ldw, int Ntot,
                  float* C, __nv_bfloat16* Chi, __nv_bfloat16* Clo, int ldc, int flipC,
                  const float* resid, const float* bias) {
    dim3 grid((Ntot + 127) / 128, ROWS / 128);
    k_hgemm<<<grid, 256, HSMEM, st>>>(Ahi, Alo, lda, K, flipA, Whi, Wlo, ldw, Ntot,
                                      C, Chi, Clo, ldc, flipC, resid, bias);
}

extern "C" void kernel_launch(void* const* d_in, const int* in_sizes, int n_in,
                              void* d_out, int out_size) {
    (void)in_sizes; (void)n_in; (void)out_size;
    const float* x         = (const float*)d_in[0];
    const float* norm_w    = (const float*)d_in[1];
    const float* out_w_blk = (const float*)d_in[2];
    const float* out_b_blk = (const float*)d_in[3];

    static cudaStream_t s2 = nullptr;
    static cudaEvent_t evA = nullptr, evB = nullptr, evC = nullptr;
    if (!s2) {
        cudaStreamCreateWithFlags(&s2, cudaStreamNonBlocking);
        cudaEventCreateWithFlags(&evA, cudaEventDisableTiming);
        cudaEventCreateWithFlags(&evB, cudaEventDisableTiming);
        cudaEventCreateWithFlags(&evC, cudaEventDisableTiming);
        cudaFuncSetAttribute(k_hgemm, cudaFuncAttributeMaxDynamicSharedMemorySize, HSMEM);
    }

    float *p_zx, *p_xBC, *p_dt, *p_Acs, *p_states, *p_prev, *p_S, *p_y;
    __nv_bfloat16 *p_XNhi, *p_XNlo, *p_Ahi, *p_Alo, *p_YChi, *p_YClo, *p_Whi, *p_Wlo;
    __nv_bfloat16 *p_WFhi, *p_WFlo;
    cudaGetSymbolAddress((void**)&p_zx,     g_zx);
    cudaGetSymbolAddress((void**)&p_xBC,    g_xBC);
    cudaGetSymbolAddress((void**)&p_dt,     g_dt);
    cudaGetSymbolAddress((void**)&p_Acs,    g_Acs);
    cudaGetSymbolAddress((void**)&p_states, g_states);
    cudaGetSymbolAddress((void**)&p_prev,   g_prev);
    cudaGetSymbolAddress((void**)&p_S,      g_S);
    cudaGetSymbolAddress((void**)&p_y,      g_y);
    cudaGetSymbolAddress((void**)&p_XNhi,   g_XNhi);
    cudaGetSymbolAddress((void**)&p_XNlo,   g_XNlo);
    cudaGetSymbolAddress((void**)&p_Ahi,    g_Ahi);
    cudaGetSymbolAddress((void**)&p_Alo,    g_Alo);
    cudaGetSymbolAddress((void**)&p_YChi,   g_YChi);
    cudaGetSymbolAddress((void**)&p_YClo,   g_YClo);
    cudaGetSymbolAddress((void**)&p_Whi,    g_Whi);
    cudaGetSymbolAddress((void**)&p_Wlo,    g_Wlo);
    cudaGetSymbolAddress((void**)&p_WFhi,   g_WFhi);
    cudaGetSymbolAddress((void**)&p_WFlo,   g_WFlo);

    k_rmsnorm<<<ROWS, 256, 0, 0>>>(x, norm_w);

    // fork: s2 joins the capture via evA BEFORE any s2 work (capture-legal order)
    cudaEventRecord(evA, 0);
    cudaStreamWaitEvent(s2, evA, 0);

    // WF weight cvt on s2 (after fork), ahead of the dir-1 chain; evC gates partial-final-#1
    cvt(s2, out_w_blk, p_WFhi, p_WFlo, (long)DM * 2 * DM, (long)DM * 2 * DM);
    cudaEventRecord(evC, s2);

    for (int d = 0; d < 2; d++) {
        cudaStream_t st = (d == 0) ? (cudaStream_t)0 : s2;
        const float* in_w    = (const float*)d_in[4 + d * 8 + 0];
        const float* conv_w  = (const float*)d_in[4 + d * 8 + 1];
        const float* conv_b  = (const float*)d_in[4 + d * 8 + 2];
        const float* dt_bias = (const float*)d_in[4 + d * 8 + 3];
        const float* A_log   = (const float*)d_in[4 + d * 8 + 4];
        const float* Dv      = (const float*)d_in[4 + d * 8 + 5];
        const float* gnw     = (const float*)d_in[4 + d * 8 + 6];
        const float* out_w   = (const float*)d_in[4 + d * 8 + 7];

        float* zx     = p_zx     + (size_t)d * ROWS * DPROJ;
        float* xBC    = p_xBC    + (size_t)d * ROWS * CONVCH;
        float* dt     = p_dt     + (size_t)d * ROWS * NH;
        float* Acs    = p_Acs    + (size_t)d * BATCH * NH * SEQL;
        float* states = p_states + (size_t)d * BATCH * NCHUNK * NH * HD * DSTATE;
        float* prev   = p_prev   + (size_t)d * BATCH * NCHUNK * NH * HD * DSTATE;
        float* S      = p_S      + (size_t)d * BATCH * NCHUNK * CH * CH;
        float* y      = p_y      + (size_t)d * ROWS * DIN;
        __nv_bfloat16* Ahi = p_Ahi + (size_t)d * ROWS * DIN;
        __nv_bfloat16* Alo = p_Alo + (size_t)d * ROWS * DIN;
        __nv_bfloat16* Whi = p_Whi + (size_t)d * NPADW * DM;
        __nv_bfloat16* Wlo = p_Wlo + (size_t)d * NPADW * DM;

        cvt(st, in_w, Whi, Wlo, (long)DPROJ * DM, (long)NPADW * DM);
        hgemm(st, p_XNhi, p_XNlo, DM, DM, d, Whi, Wlo, DM, DPROJ,
              zx, nullptr, nullptr, DPROJ, 0, nullptr, nullptr);

        k_conv_acs<<<CONV_BLOCKS + BATCH * NH * NCHUNK, 256, 0, st>>>(
            zx, xBC, conv_w, conv_b, dt_bias, A_log, dt, Acs);
        k_states_cb<<<CB_BLOCKS + BATCH * NCHUNK * NH, 256, 0, st>>>(
            xBC, dt, Acs, states, S);
        k_scan<<<BATCH * NH * 32, 256, 0, st>>>(Acs, states, prev);
        k_y<<<BATCH * NCHUNK * NH, 256, 0, st>>>(xBC, dt, Acs, prev, S, y, Dv);
        k_gnorm<<<ROWS, 256, 0, st>>>(zx, y, gnw, Ahi, Alo);

        cvt(st, out_w, Whi, Wlo, (long)DM * DIN, (long)DM * DIN);
        hgemm(st, Ahi, Alo, DIN, DIN, 0, Whi, Wlo, DIN, DM,
              nullptr, p_YChi + d * DM, p_YClo + d * DM, 2 * DM, d, nullptr, nullptr);
    }

    // partial final GEMM #1 (fwd half) on stream0: overlaps dir-1 tail.
    cudaStreamWaitEvent(0, evC, 0);
    hgemm(0, p_YChi, p_YClo, 2 * DM, DM, 0, p_WFhi, p_WFlo, 2 * DM, DM,
          (float*)d_out, nullptr, nullptr, DM, 0, x, out_b_blk);

    // join with dir-1, then partial #2 (bwd half): out += Y_bwd @ W2^T
    cudaEventRecord(evB, s2);
    cudaStreamWaitEvent(0, evB, 0);
    hgemm(0, p_YChi + DM, p_YClo + DM, 2 * DM, DM, 0, p_WFhi + DM, p_WFlo + DM, 2 * DM, DM,
          (float*)d_out, nullptr, nullptr, DM, 0, (float*)d_out, nullptr);
}

// round 16
// speedup vs baseline: 1.6018x; 1.0504x over previous
#include <cuda_runtime.h>
#include <cuda_bf16.h>
#include <math.h>
#include <stdint.h>

// ---------------- problem constants ----------------
#define BATCH   2
#define SEQL    2048
#define DM      1024
#define DIN     2048      // D_INNER
#define DSTATE  128
#define NH      32
#define HD      64
#define DPROJ   4384      // D_IN_PROJ
#define CONVCH  2304      // D_INNER + 2*D_STATE
#define NCHUNK  16
#define CH      128
#define EPSV    1e-5f
#define ROWS    (BATCH*SEQL)   // 4096
#define NPADW   4480           // 35*128, padded N for widest weight

// ---------------- scratch (device globals; [2] = per direction) ----------------
__device__ float g_zx    [2][ROWS*DPROJ];
__device__ float g_xBC   [2][ROWS*CONVCH];
__device__ float g_dt    [2][ROWS*NH];
__device__ float g_Acs   [2][BATCH*NH*SEQL];
__device__ float g_states[2][BATCH*NCHUNK*NH*HD*DSTATE];
__device__ float g_prev  [2][BATCH*NCHUNK*NH*HD*DSTATE];
__device__ float g_S     [2][BATCH*NCHUNK*CH*CH];
__device__ float g_y     [2][ROWS*DIN];

__device__ __nv_bfloat16 g_XNhi[ROWS*DM];
__device__ __nv_bfloat16 g_XNlo[ROWS*DM];
__device__ __nv_bfloat16 g_Ahi [2][ROWS*DIN];
__device__ __nv_bfloat16 g_Alo [2][ROWS*DIN];
__device__ __nv_bfloat16 g_YChi[ROWS*2*DM];
__device__ __nv_bfloat16 g_YClo[ROWS*2*DM];
__device__ __nv_bfloat16 g_Whi [2][NPADW*DM];
__device__ __nv_bfloat16 g_Wlo [2][NPADW*DM];
__device__ __nv_bfloat16 g_WFhi[2*DM*DM];
__device__ __nv_bfloat16 g_WFlo[2*DM*DM];

// ---------------- asm helpers ----------------
__device__ __forceinline__ uint32_t smem_u32(const void* p) {
    uint32_t a;
    asm("{ .reg .u64 t; cvta.to.shared.u64 t, %1; cvt.u32.u64 %0, t; }" : "=r"(a) : "l"(p));
    return a;
}
#define CP16(d, s) asm volatile("cp.async.cg.shared.global [%0], [%1], 16;" :: "r"(d), "l"(s))
#define CP_COMMIT() asm volatile("cp.async.commit_group;")
#define LDSM4(r, a) asm volatile("ldmatrix.sync.aligned.m8n8.x4.shared.b16 {%0,%1,%2,%3}, [%4];" \
    : "=r"((r)[0]), "=r"((r)[1]), "=r"((r)[2]), "=r"((r)[3]) : "r"(a))
#define MMA16816(d, a, b) asm volatile( \
    "mma.sync.aligned.m16n8k16.row.col.f32.bf16.bf16.f32 " \
    "{%0,%1,%2,%3}, {%4,%5,%6,%7}, {%8,%9}, {%0,%1,%2,%3};" \
    : "+f"((d)[0]), "+f"((d)[1]), "+f"((d)[2]), "+f"((d)[3]) \
    : "r"((a)[0]), "r"((a)[1]), "r"((a)[2]), "r"((a)[3]), "r"((b)[0]), "r"((b)[1]))

__device__ __forceinline__ uint32_t sw_addr(uint32_t base, int row, int chunk) {
    return base + (uint32_t)row * 64u + ((((uint32_t)chunk) ^ (((uint32_t)row >> 1) & 3u)) << 4);
}

__device__ __forceinline__ void hilo(float v, __nv_bfloat16& h, __nv_bfloat16& l) {
    h = __float2bfloat16(v);
    l = __float2bfloat16(v - __bfloat162float(h));
}

// ---------------- fp32 -> bf16 hi/lo conversion (weights; with zero padding) ----------------
__global__ void k_cvt(const float* __restrict__ src, __nv_bfloat16* __restrict__ hi,
                      __nv_bfloat16* __restrict__ lo, long nvalid, long total) {
    long idx = ((long)blockIdx.x * 256 + threadIdx.x) * 8;
    if (idx >= total) return;
    uint4 hq = make_uint4(0, 0, 0, 0), lq = make_uint4(0, 0, 0, 0);
    if (idx < nvalid) {
        float4 f0 = *reinterpret_cast<const float4*>(src + idx);
        float4 f1 = *reinterpret_cast<const float4*>(src + idx + 4);
        float f[8] = {f0.x, f0.y, f0.z, f0.w, f1.x, f1.y, f1.z, f1.w};
        uint32_t h[8], l[8];
#pragma unroll
        for (int i = 0; i < 8; i++) {
            __nv_bfloat16 hb, lb; hilo(f[i], hb, lb);
            h[i] = __bfloat16_as_ushort(hb);
            l[i] = __bfloat16_as_ushort(lb);
        }
        hq.x = (h[1] << 16) | h[0]; hq.y = (h[3] << 16) | h[2];
        hq.z = (h[5] << 16) | h[4]; hq.w = (h[7] << 16) | h[6];
        lq.x = (l[1] << 16) | l[0]; lq.y = (l[3] << 16) | l[2];
        lq.z = (l[5] << 16) | l[4]; lq.w = (l[7] << 16) | l[6];
    }
    *reinterpret_cast<uint4*>(hi + idx) = hq;
    *reinterpret_cast<uint4*>(lo + idx) = lq;
}

// ---------------- HMMA GEMM (3-stage cp.async pipeline; batched A-frag loads) ----------------
#define HSMEM 98304

__global__ void __launch_bounds__(256, 2) k_hgemm(
    const __nv_bfloat16* __restrict__ Ahi, const __nv_bfloat16* __restrict__ Alo,
    int lda, int K, int flipA,
    const __nv_bfloat16* __restrict__ Whi, const __nv_bfloat16* __restrict__ Wlo,
    int ldw, int Ntot, float* __restrict__ C,
    __nv_bfloat16* __restrict__ Chi, __nv_bfloat16* __restrict__ Clo,
    int ldc, int flipC,
    const float* __restrict__ resid, const float* __restrict__ bias)
{
    extern __shared__ char smraw[];
    const uint32_t sb = smem_u32(smraw);
    const int tid = threadIdx.x, lane = tid & 31, wid = tid >> 5;
    const int bm = blockIdx.y * 128, bn = blockIdx.x * 128;
    const int wm = (wid & 1) * 64, wn = (wid >> 1) * 32;

    float acc[4][4][4];
#pragma unroll
    for (int i = 0; i < 4; i++)
#pragma unroll
        for (int j = 0; j < 4; j++)
#pragma unroll
            for (int k = 0; k < 4; k++) acc[i][j][k] = 0.f;

    const int ktiles = K / 32;

    auto load_stage = [&](int s, int k0) {
        uint32_t base = sb + s * 32768;
#pragma unroll
        for (int it = 0; it < 2; it++) {
            int q = tid + it * 256;
            int r = q >> 2, c = q & 3;
            int gr = bm + r, pr = gr;
            if (flipA) pr = (gr & ~(SEQL - 1)) + (SEQL - 1 - (gr & (SEQL - 1)));
            uint32_t d = sw_addr(base, r, c);
            size_t aoff = (size_t)pr * lda + k0 + c * 8;
            CP16(d,         (const char*)(Ahi + aoff));
            CP16(d + 8192,  (const char*)(Alo + aoff));
            size_t woff = (size_t)(bn + r) * ldw + k0 + c * 8;
            CP16(d + 16384, (const char*)(Whi + woff));
            CP16(d + 24576, (const char*)(Wlo + woff));
        }
        CP_COMMIT();
    };

    load_stage(0, 0);
    load_stage(1, 32);

    int stage = 0;
    for (int i = 0; i < ktiles; i++) {
        if (i == ktiles - 1) {
            asm volatile("cp.async.wait_group 0;");
        } else {
            asm volatile("cp.async.wait_group 1;");
        }
        __syncthreads();
        if (i + 2 < ktiles) {
            int ns = stage + 2; if (ns >= 3) ns -= 3;
            load_stage(ns, (i + 2) * 32);
        }
        uint32_t base = sb + stage * 32768;
#pragma unroll
        for (int ks = 0; ks < 2; ks++) {
            const int kb = ks * 2;
            uint32_t bh[4][2], bl[4][2];
#pragma unroll
            for (int p2 = 0; p2 < 2; p2++) {
                int rr = wn + p2 * 16 + ((lane >> 4) << 3) + (lane & 7);
                int cc = kb + ((lane >> 3) & 1);
                uint32_t bd = sw_addr(base + 16384, rr, cc);
                uint32_t t[4];
                LDSM4(t, bd);
                bh[p2 * 2][0] = t[0]; bh[p2 * 2][1] = t[1];
                bh[p2 * 2 + 1][0] = t[2]; bh[p2 * 2 + 1][1] = t[3];
                LDSM4(t, bd + 8192);
                bl[p2 * 2][0] = t[0]; bl[p2 * 2][1] = t[1];
                bl[p2 * 2 + 1][0] = t[2]; bl[p2 * 2 + 1][1] = t[3];
            }
            int arow = (lane & 15);
            int acol = kb + (lane >> 4);
            uint32_t ah[4][4];
#pragma unroll
            for (int mf = 0; mf < 4; mf++)
                LDSM4(ah[mf], sw_addr(base, wm + mf * 16 + arow, acol));
#pragma unroll
            for (int mf = 0; mf < 4; mf++)
#pragma unroll
                for (int nf = 0; nf < 4; nf++) MMA16816(acc[mf][nf], ah[mf], bh[nf]);
#pragma unroll
            for (int mf = 0; mf < 4; mf++)
#pragma unroll
                for (int nf = 0; nf < 4; nf++) MMA16816(acc[mf][nf], ah[mf], bl[nf]);
            uint32_t al[4][4];
#pragma unroll
            for (int mf = 0; mf < 4; mf++)
                LDSM4(al[mf], sw_addr(base + 8192, wm + mf * 16 + arow, acol));
#pragma unroll
            for (int mf = 0; mf < 4; mf++)
#pragma unroll
                for (int nf = 0; nf < 4; nf++) MMA16816(acc[mf][nf], al[mf], bh[nf]);
        }
        if (++stage == 3) stage = 0;
    }

    // epilogue
#pragma unroll
    for (int mf = 0; mf < 4; mf++) {
        int r0 = bm + wm + mf * 16 + (lane >> 2);
        int r1 = r0 + 8;
        int p0 = r0, p1 = r1;
        if (flipC) {
            p0 = (r0 & ~(SEQL - 1)) + (SEQL - 1 - (r0 & (SEQL - 1)));
            p1 = (r1 & ~(SEQL - 1)) + (SEQL - 1 - (r1 & (SEQL - 1)));
        }
#pragma unroll
        for (int nf = 0; nf < 4; nf++) {
            int col = bn + wn + nf * 8 + (lane & 3) * 2;
            if (col >= Ntot) continue;
            float v[4] = {acc[mf][nf][0], acc[mf][nf][1], acc[mf][nf][2], acc[mf][nf][3]};
            if (bias) {
                float b0 = bias[col], b1 = bias[col + 1];
                v[0] += b0; v[1] += b1; v[2] += b0; v[3] += b1;
            }
            if (resid) {
                float2 q0 = *reinterpret_cast<const float2*>(resid + (size_t)p0 * ldc + col);
                float2 q1 = *reinterpret_cast<const float2*>(resid + (size_t)p1 * ldc + col);
                v[0] += q0.x; v[1] += q0.y; v[2] += q1.x; v[3] += q1.y;
            }
            if (Chi) {
                __nv_bfloat16 h0, l0, h1, l1;
                hilo(v[0], h0, l0); hilo(v[1], h1, l1);
                *reinterpret_cast<__nv_bfloat162*>(Chi + (size_t)p0 * ldc + col) =
                    __nv_bfloat162(h0, h1);
                *reinterpret_cast<__nv_bfloat162*>(Clo + (size_t)p0 * ldc + col) =
                    __nv_bfloat162(l0, l1);
                hilo(v[2], h0, l0); hilo(v[3], h1, l1);
                *reinterpret_cast<__nv_bfloat162*>(Chi + (size_t)p1 * ldc + col) =
                    __nv_bfloat162(h0, h1);
                *reinterpret_cast<__nv_bfloat162*>(Clo + (size_t)p1 * ldc + col) =
                    __nv_bfloat162(l0, l1);
            } else {
                *reinterpret_cast<float2*>(C + (size_t)p0 * ldc + col) = make_float2(v[0], v[1]);
                *reinterpret_cast<float2*>(C + (size_t)p1 * ldc + col) = make_float2(v[2], v[3]);
            }
        }
    }
}

// ---------------- rmsnorm -> bf16 hi/lo directly ----------------
__global__ void k_rmsnorm(const float* __restrict__ x, const float* __restrict__ w) {
    int row = blockIdx.x;
    const float* xr = x + (size_t)row * DM;
    float ss = 0.f;
    for (int i = threadIdx.x; i < DM; i += 256) { float v = xr[i]; ss += v * v; }
    __shared__ float sred[8];
    for (int o = 16; o > 0; o >>= 1) ss += __shfl_xor_sync(0xffffffffu, ss, o);
    if ((threadIdx.x & 31) == 0) sred[threadIdx.x >> 5] = ss;
    __syncthreads();
    if (threadIdx.x == 0) {
        float t = 0.f;
        for (int i = 0; i < 8; i++) t += sred[i];
        sred[0] = t;
    }
    __syncthreads();
    float scale = rsqrtf(sred[0] / (float)DM + EPSV);
    for (int i = threadIdx.x; i < DM; i += 256) {
        float v = xr[i] * scale * w[i];
        __nv_bfloat16 h, l; hilo(v, h, l);
        g_XNhi[(size_t)row * DM + i] = h;
        g_XNlo[(size_t)row * DM + i] = l;
    }
}

// ---------------- fused conv + acs (fast-math exp) ----------------
#define CONV_BLOCKS ((ROWS*CONVCH)/256)   // 36864 exact

__global__ void k_conv_acs(const float* __restrict__ zx, float* __restrict__ xBC,
                           const float* __restrict__ conv_w, const float* __restrict__ conv_b,
                           const float* __restrict__ dt_bias, const float* __restrict__ A_log,
                           float* __restrict__ dt, float* __restrict__ Acs) {
    int tid = threadIdx.x;
    if (blockIdx.x < CONV_BLOCKS) {
        int idx = blockIdx.x * 256 + tid;
        int ch = idx % CONVCH;
        int r = idx / CONVCH;
        int l = r & (SEQL - 1);
        float acc = conv_b[ch];
#pragma unroll
        for (int k = 0; k < 4; k++) {
            int ll = l - 3 + k;
            if (ll >= 0)
                acc += zx[(size_t)(r - 3 + k) * DPROJ + DIN + ch] * conv_w[ch * 4 + k];
        }
        xBC[idx] = acc / (1.f + __expf(-acc));
    } else {
        int bb = blockIdx.x - CONV_BLOCKS;
        int c = bb % NCHUNK;
        int h = (bb / NCHUNK) % NH;
        int b = bb / (NCHUNK * NH);
        int l = tid;
        __shared__ float wsum[4];
        float x = 0.f;
        if (l < 128) {
            int row = b * SEQL + c * CH + l;
            float v = zx[(size_t)row * DPROJ + DIN + CONVCH + h] + dt_bias[h];
            float dtv = (v > 20.f) ? v : log1pf(__expf(v));
            dt[row * NH + h] = dtv;
            float Aneg = -__expf(A_log[h]);
            x = Aneg * dtv;
            for (int o = 1; o < 32; o <<= 1) {
                float t = __shfl_up_sync(0xffffffffu, x, o);
                if ((l & 31) >= o) x += t;
            }
            if ((l & 31) == 31) wsum[l >> 5] = x;
        }
        __syncthreads();
        if (l < 128) {
            float add = 0.f;
            int w = l >> 5;
            for (int i = 0; i < w; i++) add += wsum[i];
            Acs[(b * NH + h) * SEQL + c * CH + l] = x + add;
        }
    }
}

// ---------------- fused states + cb ----------------
#define CB_BLOCKS (BATCH*NCHUNK)   // 32

__global__ void __launch_bounds__(256) k_states_cb(
    const float* __restrict__ xBC, const float* __restrict__ dt,
    const float* __restrict__ Acs, float* __restrict__ states,
    float* __restrict__ S) {
    __shared__ float smu[2 * 32 * 132];
    int tid = threadIdx.x;
    int tx = tid & 15, ty = tid >> 4;

    if (blockIdx.x < CB_BLOCKS) {
        int c = blockIdx.x % NCHUNK, b = blockIdx.x / NCHUNK;
        float (*sC)[132]  = reinterpret_cast<float(*)[132]>(smu);
        float (*sBm)[132] = reinterpret_cast<float(*)[132]>(smu + 32 * 132);
        float acc[8][8];
#pragma unroll
        for (int i = 0; i < 8; i++)
#pragma unroll
            for (int j = 0; j < 8; j++) acc[i][j] = 0.f;

        for (int k0 = 0; k0 < DSTATE; k0 += 32) {
            for (int i = tid; i < 32 * 128; i += 256) {
                int kk = i & 31, l = i >> 5;
                int row = b * SEQL + c * CH + l;
                sC[kk][l]  = xBC[(size_t)row * CONVCH + DIN + DSTATE + k0 + kk];
                sBm[kk][l] = xBC[(size_t)row * CONVCH + DIN + k0 + kk];
            }
            __syncthreads();
#pragma unroll
            for (int kk = 0; kk < 32; kk++) {
                float a[8], bv[8];
#pragma unroll
                for (int i = 0; i < 8; i++) a[i] = sC[kk][ty * 8 + i];
#pragma unroll
                for (int j = 0; j < 8; j++) bv[j] = sBm[kk][tx * 8 + j];
#pragma unroll
                for (int i = 0; i < 8; i++)
#pragma unroll
                    for (int j = 0; j < 8; j++) acc[i][j] += a[i] * bv[j];
            }
            __syncthreads();
        }
        size_t base = (size_t)(b * NCHUNK + c) * CH * CH;
#pragma unroll
        for (int i = 0; i < 8; i++)
#pragma unroll
            for (int j = 0; j < 8; j++)
                S[base + (ty * 8 + i) * CH + tx * 8 + j] = acc[i][j];
    } else {
        int bb = blockIdx.x - CB_BLOCKS;
        int h = bb % NH;
        int c = (bb / NH) % NCHUNK;
        int b = bb / (NH * NCHUNK);
        float (*sX)[64]  = reinterpret_cast<float(*)[64]>(smu);
        float (*sB)[132] = reinterpret_cast<float(*)[132]>(smu + 32 * 64);
        float acc[4][8];
#pragma unroll
        for (int i = 0; i < 4; i++)
#pragma unroll
            for (int j = 0; j < 8; j++) acc[i][j] = 0.f;

        const float* AcsRow = Acs + (b * NH + h) * SEQL + c * CH;
        float AcsLast = AcsRow[127];

        for (int lt = 0; lt < 4; lt++) {
            for (int i = tid; i < 32 * 64; i += 256) {
                int l = i >> 6, p = i & 63;
                int row = b * SEQL + c * CH + lt * 32 + l;
                float w = dt[row * NH + h] * __expf(AcsLast - AcsRow[lt * 32 + l]);
                sX[l][p] = xBC[(size_t)row * CONVCH + h * HD + p] * w;
            }
            for (int i = tid; i < 32 * 128; i += 256) {
                int l = i >> 7, n = i & 127;
                int row = b * SEQL + c * CH + lt * 32 + l;
                sB[l][n] = xBC[(size_t)row * CONVCH + DIN + n];
            }
            __syncthreads();
#pragma unroll
            for (int l = 0; l < 32; l++) {
                float xv[4], bv[8];
#pragma unroll
                for (int i = 0; i < 4; i++) xv[i] = sX[l][ty * 4 + i];
#pragma unroll
                for (int j = 0; j < 8; j++) bv[j] = sB[l][tx * 8 + j];
#pragma unroll
                for (int i = 0; i < 4; i++)
#pragma unroll
                    for (int j = 0; j < 8; j++) acc[i][j] += xv[i] * bv[j];
            }
            __syncthreads();
        }
        size_t base = ((size_t)(b * NCHUNK + c) * NH + h) * HD * DSTATE;
#pragma unroll
        for (int i = 0; i < 4; i++)
#pragma unroll
            for (int j = 0; j < 8; j++)
                states[base + (ty * 4 + i) * DSTATE + tx * 8 + j] = acc[i][j];
    }
}

// ---------------- chunk scan (2048 blocks) ----------------
__global__ void k_scan(const float* __restrict__ Acs, const float* __restrict__ states,
                       float* __restrict__ prev) {
    int seg = blockIdx.x & 31;
    int h = (blockIdx.x >> 5) % NH;
    int b = blockIdx.x / (32 * NH);
    int e = seg * 256 + threadIdx.x;
    float s = 0.f;
    for (int c = 0; c < NCHUNK; c++) {
        float cd = __expf(Acs[(b * NH + h) * SEQL + c * CH + 127]);
        size_t base = ((size_t)(b * NCHUNK + c) * NH + h) * HD * DSTATE;
        prev[base + e] = s;
        s = s * cd + states[base + e];
    }
}

// ---------------- Y = Y_diag + Y_off + xs*D  — HMMA version ----------------
// Per (b,c,h): Y[128 l][64 p] = G(128x128) @ Xdt(128x64)  +  exp(Acs[l]) * Cx(128x128) @ prev^T(128x64)
// Both phases run on tensor cores with bf16 hi/lo 3-term split; K processed in 32-wide tiles.
// A tile [128][32] pad 40; B tile [64][32] pad 40 (row-major N x K, like W in hgemm).
__global__ void __launch_bounds__(256) k_y(
    const float* __restrict__ xBC, const float* __restrict__ dt,
    const float* __restrict__ Acs, const float* __restrict__ prev,
    const float* __restrict__ S, float* __restrict__ y,
    const float* __restrict__ Dvec) {
    int h = blockIdx.x % NH;
    int c = (blockIdx.x / NH) % NCHUNK;
    int b = blockIdx.x / (NH * NCHUNK);

    __shared__ __align__(16) char sm[31232];
    __nv_bfloat16* sAh = reinterpret_cast<__nv_bfloat16*>(sm);            // 128x40
    __nv_bfloat16* sAl = reinterpret_cast<__nv_bfloat16*>(sm + 10240);
    __nv_bfloat16* sBh = reinterpret_cast<__nv_bfloat16*>(sm + 20480);    // 64x40
    __nv_bfloat16* sBl = reinterpret_cast<__nv_bfloat16*>(sm + 25600);
    float* sAcs = reinterpret_cast<float*>(sm + 30720);
    const uint32_t uAh = smem_u32(sAh), uAl = smem_u32(sAl);
    const uint32_t uBh = smem_u32(sBh), uBl = smem_u32(sBl);

    int tid = threadIdx.x, lane = tid & 31, wid = tid >> 5;
    int wm = (wid & 3) * 32, wn = (wid >> 2) * 32;

    if (tid < 128) sAcs[tid] = Acs[(b * NH + h) * SEQL + c * CH + tid];
    __syncthreads();

    float accA[2][4][4], accB[2][4][4];
#pragma unroll
    for (int i = 0; i < 2; i++)
#pragma unroll
        for (int j = 0; j < 4; j++)
#pragma unroll
            for (int k = 0; k < 4; k++) { accA[i][j][k] = 0.f; accB[i][j][k] = 0.f; }

    // warp-tile MMA over one K=32 slice (A:[128][32] pad40, B:[64][32] pad40)
    auto mma_tile = [&](float (&acc)[2][4][4]) {
#pragma unroll
        for (int ks = 0; ks < 2; ks++) {
            uint32_t bh[4][2], bl[4][2];
#pragma unroll
            for (int p2 = 0; p2 < 2; p2++) {
                int rr = wn + p2 * 16 + ((lane >> 4) << 3) + (lane & 7);
                int cc = ks * 2 + ((lane >> 3) & 1);
                uint32_t t[4];
                LDSM4(t, uBh + (uint32_t)rr * 80u + (uint32_t)cc * 16u);
                bh[p2 * 2][0] = t[0]; bh[p2 * 2][1] = t[1];
                bh[p2 * 2 + 1][0] = t[2]; bh[p2 * 2 + 1][1] = t[3];
                LDSM4(t, uBl + (uint32_t)rr * 80u + (uint32_t)cc * 16u);
                bl[p2 * 2][0] = t[0]; bl[p2 * 2][1] = t[1];
                bl[p2 * 2 + 1][0] = t[2]; bl[p2 * 2 + 1][1] = t[3];
            }
            int ar = lane & 15;
            int ac = ks * 2 + (lane >> 4);
#pragma unroll
            for (int mf = 0; mf < 2; mf++) {
                uint32_t a[4];
                LDSM4(a, uAh + (uint32_t)(wm + mf * 16 + ar) * 80u + (uint32_t)ac * 16u);
#pragma unroll
                for (int nf = 0; nf < 4; nf++) MMA16816(acc[mf][nf], a, bh[nf]);
#pragma unroll
                for (int nf = 0; nf < 4; nf++) MMA16816(acc[mf][nf], a, bl[nf]);
                LDSM4(a, uAl + (uint32_t)(wm + mf * 16 + ar) * 80u + (uint32_t)ac * 16u);
#pragma unroll
                for (int nf = 0; nf < 4; nf++) MMA16816(acc[mf][nf], a, bh[nf]);
            }
        }
    };

    size_t Sbase = (size_t)(b * NCHUNK + c) * CH * CH;
    // ---- phase A: Y_diag = G @ Xdt ----
    for (int st = 0; st < 4; st++) {
        for (int i = tid; i < 128 * 32; i += 256) {
            int s = i & 31, l = i >> 5;
            int sg = st * 32 + s;
            float v = (sg <= l) ? S[Sbase + l * CH + sg] * __expf(sAcs[l] - sAcs[sg]) : 0.f;
            __nv_bfloat16 hh, ll; hilo(v, hh, ll);
            sAh[l * 40 + s] = hh; sAl[l * 40 + s] = ll;
        }
        for (int i = tid; i < 64 * 32; i += 256) {
            int p = i & 63, s = i >> 6;
            int row = b * SEQL + c * CH + st * 32 + s;
            float v = xBC[(size_t)row * CONVCH + h * HD + p] * dt[row * NH + h];
            __nv_bfloat16 hh, ll; hilo(v, hh, ll);
            sBh[p * 40 + s] = hh; sBl[p * 40 + s] = ll;   // transposed store: [p][s]
        }
        __syncthreads();
        mma_tile(accA);
        __syncthreads();
    }
    // ---- phase B: Y_off_core = Cx @ prev^T ----
    size_t Pbase = ((size_t)(b * NCHUNK + c) * NH + h) * HD * DSTATE;
    for (int nt = 0; nt < 4; nt++) {
        for (int i = tid; i < 128 * 32; i += 256) {
            int n = i & 31, l = i >> 5;
            int row = b * SEQL + c * CH + l;
            float v = xBC[(size_t)row * CONVCH + DIN + DSTATE + nt * 32 + n];
            __nv_bfloat16 hh, ll; hilo(v, hh, ll);
            sAh[l * 40 + n] = hh; sAl[l * 40 + n] = ll;
        }
        for (int i = tid; i < 64 * 32; i += 256) {
            int n = i & 31, p = i >> 5;
            float v = prev[Pbase + (size_t)p * DSTATE + nt * 32 + n];
            __nv_bfloat16 hh, ll; hilo(v, hh, ll);
            sBh[p * 40 + n] = hh; sBl[p * 40 + n] = ll;   // already [p][n] row-major
        }
        __syncthreads();
        mma_tile(accB);
        __syncthreads();
    }

    // ---- combine + skip (fragment epilogue) ----
    float Dh = Dvec[h];
#pragma unroll
    for (int mf = 0; mf < 2; mf++) {
        int r0 = wm + mf * 16 + (lane >> 2);
        int r1 = r0 + 8;
        float el0 = __expf(sAcs[r0]);
        float el1 = __expf(sAcs[r1]);
        int rg0 = b * SEQL + c * CH + r0;
        int rg1 = b * SEQL + c * CH + r1;
#pragma unroll
        for (int nf = 0; nf < 4; nf++) {
            int col = wn + nf * 8 + (lane & 3) * 2;
            float xs00 = xBC[(size_t)rg0 * CONVCH + h * HD + col];
            float xs01 = xBC[(size_t)rg0 * CONVCH + h * HD + col + 1];
            float xs10 = xBC[(size_t)rg1 * CONVCH + h * HD + col];
            float xs11 = xBC[(size_t)rg1 * CONVCH + h * HD + col + 1];
            y[(size_t)rg0 * DIN + h * HD + col]     = accA[mf][nf][0] + el0 * accB[mf][nf][0] + xs00 * Dh;
            y[(size_t)rg0 * DIN + h * HD + col + 1] = accA[mf][nf][1] + el0 * accB[mf][nf][1] + xs01 * Dh;
            y[(size_t)rg1 * DIN + h * HD + col]     = accA[mf][nf][2] + el1 * accB[mf][nf][2] + xs10 * Dh;
            y[(size_t)rg1 * DIN + h * HD + col + 1] = accA[mf][nf][3] + el1 * accB[mf][nf][3] + xs11 * Dh;
        }
    }
}

// ---------------- gated rmsnorm -> bf16 hi/lo directly (fast-math silu) ----------------
__global__ void k_gnorm(const float* __restrict__ zx, const float* __restrict__ y,
                        const float* __restrict__ gnorm_w,
                        __nv_bfloat16* __restrict__ outHi, __nv_bfloat16* __restrict__ outLo) {
    int row = blockIdx.x;
    __shared__ float st[DIN];
    __shared__ float sred[8];
    float ss = 0.f;
    for (int i = threadIdx.x; i < DIN; i += 256) {
        float z = zx[(size_t)row * DPROJ + i];
        float t = y[(size_t)row * DIN + i] * (z / (1.f + __expf(-z)));
        st[i] = t;
        ss += t * t;
    }
    for (int o = 16; o > 0; o >>= 1) ss += __shfl_xor_sync(0xffffffffu, ss, o);
    if ((threadIdx.x & 31) == 0) sred[threadIdx.x >> 5] = ss;
    __syncthreads();
    if (threadIdx.x == 0) {
        float t = 0.f;
        for (int i = 0; i < 8; i++) t += sred[i];
        sred[0] = t;
    }
    __syncthreads();
    float scale = rsqrtf(sred[0] / (float)DIN + EPSV);
    for (int i = threadIdx.x; i < DIN; i += 256) {
        float v = st[i] * scale * gnorm_w[i];
        __nv_bfloat16 h, l; hilo(v, h, l);
        outHi[(size_t)row * DIN + i] = h;
        outLo[(size_t)row * DIN + i] = l;
    }
}

// ---------------- host helpers ----------------
static void cvt(cudaStream_t st, const float* src, __nv_bfloat16* hi, __nv_bfloat16* lo,
                long nvalid, long total) {
    long blocks = (total / 8 + 255) / 256;
    k_cvt<<<(unsigned)blocks, 256, 0, st>>>(src, hi, lo, nvalid, total);
}

static void hgemm(cudaStream_t st,
                  const __nv_bfloat16* Ahi, const __nv_bfloat16* Alo, int lda, int K, int flipA,
                  const __nv_bfloat16* Whi, const __nv_bfloat16* Wlo, int ldw, int Ntot,
                  float* C, __nv_bfloat16* Chi, __nv_bfloat16* Clo, int ldc, int flipC,
                  const float* resid, const float* bias) {
    dim3 grid((Ntot + 127) / 128, ROWS / 128);
    k_hgemm<<<grid, 256, HSMEM, st>>>(Ahi, Alo, lda, K, flipA, Whi, Wlo, ldw, Ntot,
                                      C, Chi, Clo, ldc, flipC, resid, bias);
}

extern "C" void kernel_launch(void* const* d_in, const int* in_sizes, int n_in,
                              void* d_out, int out_size) {
    (void)in_sizes; (void)n_in; (void)out_size;
    const float* x         = (const float*)d_in[0];
    const float* norm_w    = (const float*)d_in[1];
    const float* out_w_blk = (const float*)d_in[2];
    const float* out_b_blk = (const float*)d_in[3];

    static cudaStream_t s2 = nullptr;
    static cudaEvent_t evA = nullptr, evB = nullptr, evC = nullptr;
    if (!s2) {
        cudaStreamCreateWithFlags(&s2, cudaStreamNonBlocking);
        cudaEventCreateWithFlags(&evA, cudaEventDisableTiming);
        cudaEventCreateWithFlags(&evB, cudaEventDisableTiming);
        cudaEventCreateWithFlags(&evC, cudaEventDisableTiming);
        cudaFuncSetAttribute(k_hgemm, cudaFuncAttributeMaxDynamicSharedMemorySize, HSMEM);
    }

    float *p_zx, *p_xBC, *p_dt, *p_Acs, *p_states, *p_prev, *p_S, *p_y;
    __nv_bfloat16 *p_XNhi, *p_XNlo, *p_Ahi, *p_Alo, *p_YChi, *p_YClo, *p_Whi, *p_Wlo;
    __nv_bfloat16 *p_WFhi, *p_WFlo;
    cudaGetSymbolAddress((void**)&p_zx,     g_zx);
    cudaGetSymbolAddress((void**)&p_xBC,    g_xBC);
    cudaGetSymbolAddress((void**)&p_dt,     g_dt);
    cudaGetSymbolAddress((void**)&p_Acs,    g_Acs);
    cudaGetSymbolAddress((void**)&p_states, g_states);
    cudaGetSymbolAddress((void**)&p_prev,   g_prev);
    cudaGetSymbolAddress((void**)&p_S,      g_S);
    cudaGetSymbolAddress((void**)&p_y,      g_y);
    cudaGetSymbolAddress((void**)&p_XNhi,   g_XNhi);
    cudaGetSymbolAddress((void**)&p_XNlo,   g_XNlo);
    cudaGetSymbolAddress((void**)&p_Ahi,    g_Ahi);
    cudaGetSymbolAddress((void**)&p_Alo,    g_Alo);
    cudaGetSymbolAddress((void**)&p_YChi,   g_YChi);
    cudaGetSymbolAddress((void**)&p_YClo,   g_YClo);
    cudaGetSymbolAddress((void**)&p_Whi,    g_Whi);
    cudaGetSymbolAddress((void**)&p_Wlo,    g_Wlo);
    cudaGetSymbolAddress((void**)&p_WFhi,   g_WFhi);
    cudaGetSymbolAddress((void**)&p_WFlo,   g_WFlo);

    k_rmsnorm<<<ROWS, 256, 0, 0>>>(x, norm_w);

    // fork: s2 joins the capture via evA BEFORE any s2 work (capture-legal order)
    cudaEventRecord(evA, 0);
    cudaStreamWaitEvent(s2, evA, 0);

    // WF weight cvt on s2 (after fork), ahead of the dir-1 chain; evC gates partial-final-#1
    cvt(s2, out_w_blk, p_WFhi, p_WFlo, (long)DM * 2 * DM, (long)DM * 2 * DM);
    cudaEventRecord(evC, s2);

    for (int d = 0; d < 2; d++) {
        cudaStream_t st = (d == 0) ? (cudaStream_t)0 : s2;
        const float* in_w    = (const float*)d_in[4 + d * 8 + 0];
        const float* conv_w  = (const float*)d_in[4 + d * 8 + 1];
        const float* conv_b  = (const float*)d_in[4 + d * 8 + 2];
        const float* dt_bias = (const float*)d_in[4 + d * 8 + 3];
        const float* A_log   = (const float*)d_in[4 + d * 8 + 4];
        const float* Dv      = (const float*)d_in[4 + d * 8 + 5];
        const float* gnw     = (const float*)d_in[4 + d * 8 + 6];
        const float* out_w   = (const float*)d_in[4 + d * 8 + 7];

        float* zx     = p_zx     + (size_t)d * ROWS * DPROJ;
        float* xBC    = p_xBC    + (size_t)d * ROWS * CONVCH;
        float* dt     = p_dt     + (size_t)d * ROWS * NH;
        float* Acs    = p_Acs    + (size_t)d * BATCH * NH * SEQL;
        float* states = p_states + (size_t)d * BATCH * NCHUNK * NH * HD * DSTATE;
        float* prev   = p_prev   + (size_t)d * BATCH * NCHUNK * NH * HD * DSTATE;
        float* S      = p_S      + (size_t)d * BATCH * NCHUNK * CH * CH;
        float* y      = p_y      + (size_t)d * ROWS * DIN;
        __nv_bfloat16* Ahi = p_Ahi + (size_t)d * ROWS * DIN;
        __nv_bfloat16* Alo = p_Alo + (size_t)d * ROWS * DIN;
        __nv_bfloat16* Whi = p_Whi + (size_t)d * NPADW * DM;
        __nv_bfloat16* Wlo = p_Wlo + (size_t)d * NPADW * DM;

        cvt(st, in_w, Whi, Wlo, (long)DPROJ * DM, (long)NPADW * DM);
        hgemm(st, p_XNhi, p_XNlo, DM, DM, d, Whi, Wlo, DM, DPROJ,
              zx, nullptr, nullptr, DPROJ, 0, nullptr, nullptr);

        k_conv_acs<<<CONV_BLOCKS + BATCH * NH * NCHUNK, 256, 0, st>>>(
            zx, xBC, conv_w, conv_b, dt_bias, A_log, dt, Acs);
        k_states_cb<<<CB_BLOCKS + BATCH * NCHUNK * NH, 256, 0, st>>>(
            xBC, dt, Acs, states, S);
        k_scan<<<BATCH * NH * 32, 256, 0, st>>>(Acs, states, prev);
        k_y<<<BATCH * NCHUNK * NH, 256, 0, st>>>(xBC, dt, Acs, prev, S, y, Dv);
        k_gnorm<<<ROWS, 256, 0, st>>>(zx, y, gnw, Ahi, Alo);

        cvt(st, out_w, Whi, Wlo, (long)DM * DIN, (long)DM * DIN);
        hgemm(st, Ahi, Alo, DIN, DIN, 0, Whi, Wlo, DIN, DM,
              nullptr, p_YChi + d * DM, p_YClo + d * DM, 2 * DM, d, nullptr, nullptr);
    }

    // partial final GEMM #1 (fwd half) on stream0: overlaps dir-1 tail.
    cudaStreamWaitEvent(0, evC, 0);
    hgemm(0, p_YChi, p_YClo, 2 * DM, DM, 0, p_WFhi, p_WFlo, 2 * DM, DM,
          (float*)d_out, nullptr, nullptr, DM, 0, x, out_b_blk);

    // join with dir-1, then partial #2 (bwd half): out += Y_bwd @ W2^T
    cudaEventRecord(evB, s2);
    cudaStreamWaitEvent(0, evB, 0);
    hgemm(0, p_YChi + DM, p_YClo + DM, 2 * DM, DM, 0, p_WFhi + DM, p_WFlo + DM, 2 * DM, DM,
          (float*)d_out, nullptr, nullptr, DM, 0, (float*)d_out, nullptr);
}

// round 17
// speedup vs baseline: 1.7242x; 1.0764x over previous
#include <cuda_runtime.h>
#include <cuda_bf16.h>
#include <math.h>
#include <stdint.h>

// ---------------- problem constants ----------------
#define BATCH   2
#define SEQL    2048
#define DM      1024
#define DIN     2048      // D_INNER
#define DSTATE  128
#define NH      32
#define HD      64
#define DPROJ   4384      // D_IN_PROJ
#define CONVCH  2304      // D_INNER + 2*D_STATE
#define NCHUNK  16
#define CH      128
#define EPSV    1e-5f
#define ROWS    (BATCH*SEQL)   // 4096
#define NPADW   4480           // 35*128, padded N for widest weight

// ---------------- scratch (device globals; [2] = per direction) ----------------
__device__ float g_zx    [2][ROWS*DPROJ];
__device__ float g_xBC   [2][ROWS*CONVCH];
__device__ float g_dt    [2][ROWS*NH];
__device__ float g_Acs   [2][BATCH*NH*SEQL];
__device__ float g_states[2][BATCH*NCHUNK*NH*HD*DSTATE];
__device__ float g_prev  [2][BATCH*NCHUNK*NH*HD*DSTATE];
__device__ float g_S     [2][BATCH*NCHUNK*CH*CH];
__device__ float g_y     [2][ROWS*DIN];

__device__ __nv_bfloat16 g_XNhi[ROWS*DM];
__device__ __nv_bfloat16 g_XNlo[ROWS*DM];
__device__ __nv_bfloat16 g_Ahi [2][ROWS*DIN];
__device__ __nv_bfloat16 g_Alo [2][ROWS*DIN];
__device__ __nv_bfloat16 g_YChi[ROWS*2*DM];
__device__ __nv_bfloat16 g_YClo[ROWS*2*DM];
__device__ __nv_bfloat16 g_Whi [2][NPADW*DM];
__device__ __nv_bfloat16 g_Wlo [2][NPADW*DM];
__device__ __nv_bfloat16 g_WFhi[2*DM*DM];
__device__ __nv_bfloat16 g_WFlo[2*DM*DM];

// ---------------- asm helpers ----------------
__device__ __forceinline__ uint32_t smem_u32(const void* p) {
    uint32_t a;
    asm("{ .reg .u64 t; cvta.to.shared.u64 t, %1; cvt.u32.u64 %0, t; }" : "=r"(a) : "l"(p));
    return a;
}
#define CP16(d, s) asm volatile("cp.async.cg.shared.global [%0], [%1], 16;" :: "r"(d), "l"(s))
#define CP_COMMIT() asm volatile("cp.async.commit_group;")
#define LDSM4(r, a) asm volatile("ldmatrix.sync.aligned.m8n8.x4.shared.b16 {%0,%1,%2,%3}, [%4];" \
    : "=r"((r)[0]), "=r"((r)[1]), "=r"((r)[2]), "=r"((r)[3]) : "r"(a))
#define MMA16816(d, a, b) asm volatile( \
    "mma.sync.aligned.m16n8k16.row.col.f32.bf16.bf16.f32 " \
    "{%0,%1,%2,%3}, {%4,%5,%6,%7}, {%8,%9}, {%0,%1,%2,%3};" \
    : "+f"((d)[0]), "+f"((d)[1]), "+f"((d)[2]), "+f"((d)[3]) \
    : "r"((a)[0]), "r"((a)[1]), "r"((a)[2]), "r"((a)[3]), "r"((b)[0]), "r"((b)[1]))

__device__ __forceinline__ uint32_t sw_addr(uint32_t base, int row, int chunk) {
    return base + (uint32_t)row * 64u + ((((uint32_t)chunk) ^ (((uint32_t)row >> 1) & 3u)) << 4);
}

__device__ __forceinline__ void hilo(float v, __nv_bfloat16& h, __nv_bfloat16& l) {
    h = __float2bfloat16(v);
    l = __float2bfloat16(v - __bfloat162float(h));
}

// ---------------- fp32 -> bf16 hi/lo conversion (weights; with zero padding) ----------------
__global__ void k_cvt(const float* __restrict__ src, __nv_bfloat16* __restrict__ hi,
                      __nv_bfloat16* __restrict__ lo, long nvalid, long total) {
    long idx = ((long)blockIdx.x * 256 + threadIdx.x) * 8;
    if (idx >= total) return;
    uint4 hq = make_uint4(0, 0, 0, 0), lq = make_uint4(0, 0, 0, 0);
    if (idx < nvalid) {
        float4 f0 = *reinterpret_cast<const float4*>(src + idx);
        float4 f1 = *reinterpret_cast<const float4*>(src + idx + 4);
        float f[8] = {f0.x, f0.y, f0.z, f0.w, f1.x, f1.y, f1.z, f1.w};
        uint32_t h[8], l[8];
#pragma unroll
        for (int i = 0; i < 8; i++) {
            __nv_bfloat16 hb, lb; hilo(f[i], hb, lb);
            h[i] = __bfloat16_as_ushort(hb);
            l[i] = __bfloat16_as_ushort(lb);
        }
        hq.x = (h[1] << 16) | h[0]; hq.y = (h[3] << 16) | h[2];
        hq.z = (h[5] << 16) | h[4]; hq.w = (h[7] << 16) | h[6];
        lq.x = (l[1] << 16) | l[0]; lq.y = (l[3] << 16) | l[2];
        lq.z = (l[5] << 16) | l[4]; lq.w = (l[7] << 16) | l[6];
    }
    *reinterpret_cast<uint4*>(hi + idx) = hq;
    *reinterpret_cast<uint4*>(lo + idx) = lq;
}

// ---------------- HMMA GEMM (3-stage cp.async pipeline; batched A-frag loads) ----------------
#define HSMEM 98304

__global__ void __launch_bounds__(256, 2) k_hgemm(
    const __nv_bfloat16* __restrict__ Ahi, const __nv_bfloat16* __restrict__ Alo,
    int lda, int K, int flipA,
    const __nv_bfloat16* __restrict__ Whi, const __nv_bfloat16* __restrict__ Wlo,
    int ldw, int Ntot, float* __restrict__ C,
    __nv_bfloat16* __restrict__ Chi, __nv_bfloat16* __restrict__ Clo,
    int ldc, int flipC,
    const float* __restrict__ resid, const float* __restrict__ bias)
{
    extern __shared__ char smraw[];
    const uint32_t sb = smem_u32(smraw);
    const int tid = threadIdx.x, lane = tid & 31, wid = tid >> 5;
    const int bm = blockIdx.y * 128, bn = blockIdx.x * 128;
    const int wm = (wid & 1) * 64, wn = (wid >> 1) * 32;

    float acc[4][4][4];
#pragma unroll
    for (int i = 0; i < 4; i++)
#pragma unroll
        for (int j = 0; j < 4; j++)
#pragma unroll
            for (int k = 0; k < 4; k++) acc[i][j][k] = 0.f;

    const int ktiles = K / 32;

    auto load_stage = [&](int s, int k0) {
        uint32_t base = sb + s * 32768;
#pragma unroll
        for (int it = 0; it < 2; it++) {
            int q = tid + it * 256;
            int r = q >> 2, c = q & 3;
            int gr = bm + r, pr = gr;
            if (flipA) pr = (gr & ~(SEQL - 1)) + (SEQL - 1 - (gr & (SEQL - 1)));
            uint32_t d = sw_addr(base, r, c);
            size_t aoff = (size_t)pr * lda + k0 + c * 8;
            CP16(d,         (const char*)(Ahi + aoff));
            CP16(d + 8192,  (const char*)(Alo + aoff));
            size_t woff = (size_t)(bn + r) * ldw + k0 + c * 8;
            CP16(d + 16384, (const char*)(Whi + woff));
            CP16(d + 24576, (const char*)(Wlo + woff));
        }
        CP_COMMIT();
    };

    load_stage(0, 0);
    load_stage(1, 32);

    int stage = 0;
    for (int i = 0; i < ktiles; i++) {
        if (i == ktiles - 1) {
            asm volatile("cp.async.wait_group 0;");
        } else {
            asm volatile("cp.async.wait_group 1;");
        }
        __syncthreads();
        if (i + 2 < ktiles) {
            int ns = stage + 2; if (ns >= 3) ns -= 3;
            load_stage(ns, (i + 2) * 32);
        }
        uint32_t base = sb + stage * 32768;
#pragma unroll
        for (int ks = 0; ks < 2; ks++) {
            const int kb = ks * 2;
            uint32_t bh[4][2], bl[4][2];
#pragma unroll
            for (int p2 = 0; p2 < 2; p2++) {
                int rr = wn + p2 * 16 + ((lane >> 4) << 3) + (lane & 7);
                int cc = kb + ((lane >> 3) & 1);
                uint32_t bd = sw_addr(base + 16384, rr, cc);
                uint32_t t[4];
                LDSM4(t, bd);
                bh[p2 * 2][0] = t[0]; bh[p2 * 2][1] = t[1];
                bh[p2 * 2 + 1][0] = t[2]; bh[p2 * 2 + 1][1] = t[3];
                LDSM4(t, bd + 8192);
                bl[p2 * 2][0] = t[0]; bl[p2 * 2][1] = t[1];
                bl[p2 * 2 + 1][0] = t[2]; bl[p2 * 2 + 1][1] = t[3];
            }
            int arow = (lane & 15);
            int acol = kb + (lane >> 4);
            uint32_t ah[4][4];
#pragma unroll
            for (int mf = 0; mf < 4; mf++)
                LDSM4(ah[mf], sw_addr(base, wm + mf * 16 + arow, acol));
#pragma unroll
            for (int mf = 0; mf < 4; mf++)
#pragma unroll
                for (int nf = 0; nf < 4; nf++) MMA16816(acc[mf][nf], ah[mf], bh[nf]);
#pragma unroll
            for (int mf = 0; mf < 4; mf++)
#pragma unroll
                for (int nf = 0; nf < 4; nf++) MMA16816(acc[mf][nf], ah[mf], bl[nf]);
            uint32_t al[4][4];
#pragma unroll
            for (int mf = 0; mf < 4; mf++)
                LDSM4(al[mf], sw_addr(base + 8192, wm + mf * 16 + arow, acol));
#pragma unroll
            for (int mf = 0; mf < 4; mf++)
#pragma unroll
                for (int nf = 0; nf < 4; nf++) MMA16816(acc[mf][nf], al[mf], bh[nf]);
        }
        if (++stage == 3) stage = 0;
    }

    // epilogue
#pragma unroll
    for (int mf = 0; mf < 4; mf++) {
        int r0 = bm + wm + mf * 16 + (lane >> 2);
        int r1 = r0 + 8;
        int p0 = r0, p1 = r1;
        if (flipC) {
            p0 = (r0 & ~(SEQL - 1)) + (SEQL - 1 - (r0 & (SEQL - 1)));
            p1 = (r1 & ~(SEQL - 1)) + (SEQL - 1 - (r1 & (SEQL - 1)));
        }
#pragma unroll
        for (int nf = 0; nf < 4; nf++) {
            int col = bn + wn + nf * 8 + (lane & 3) * 2;
            if (col >= Ntot) continue;
            float v[4] = {acc[mf][nf][0], acc[mf][nf][1], acc[mf][nf][2], acc[mf][nf][3]};
            if (bias) {
                float b0 = bias[col], b1 = bias[col + 1];
                v[0] += b0; v[1] += b1; v[2] += b0; v[3] += b1;
            }
            if (resid) {
                float2 q0 = *reinterpret_cast<const float2*>(resid + (size_t)p0 * ldc + col);
                float2 q1 = *reinterpret_cast<const float2*>(resid + (size_t)p1 * ldc + col);
                v[0] += q0.x; v[1] += q0.y; v[2] += q1.x; v[3] += q1.y;
            }
            if (Chi) {
                __nv_bfloat16 h0, l0, h1, l1;
                hilo(v[0], h0, l0); hilo(v[1], h1, l1);
                *reinterpret_cast<__nv_bfloat162*>(Chi + (size_t)p0 * ldc + col) =
                    __nv_bfloat162(h0, h1);
                *reinterpret_cast<__nv_bfloat162*>(Clo + (size_t)p0 * ldc + col) =
                    __nv_bfloat162(l0, l1);
                hilo(v[2], h0, l0); hilo(v[3], h1, l1);
                *reinterpret_cast<__nv_bfloat162*>(Chi + (size_t)p1 * ldc + col) =
                    __nv_bfloat162(h0, h1);
                *reinterpret_cast<__nv_bfloat162*>(Clo + (size_t)p1 * ldc + col) =
                    __nv_bfloat162(l0, l1);
            } else {
                *reinterpret_cast<float2*>(C + (size_t)p0 * ldc + col) = make_float2(v[0], v[1]);
                *reinterpret_cast<float2*>(C + (size_t)p1 * ldc + col) = make_float2(v[2], v[3]);
            }
        }
    }
}

// ---------------- rmsnorm -> bf16 hi/lo directly ----------------
__global__ void k_rmsnorm(const float* __restrict__ x, const float* __restrict__ w) {
    int row = blockIdx.x;
    const float* xr = x + (size_t)row * DM;
    float ss = 0.f;
    for (int i = threadIdx.x; i < DM; i += 256) { float v = xr[i]; ss += v * v; }
    __shared__ float sred[8];
    for (int o = 16; o > 0; o >>= 1) ss += __shfl_xor_sync(0xffffffffu, ss, o);
    if ((threadIdx.x & 31) == 0) sred[threadIdx.x >> 5] = ss;
    __syncthreads();
    if (threadIdx.x == 0) {
        float t = 0.f;
        for (int i = 0; i < 8; i++) t += sred[i];
        sred[0] = t;
    }
    __syncthreads();
    float scale = rsqrtf(sred[0] / (float)DM + EPSV);
    for (int i = threadIdx.x; i < DM; i += 256) {
        float v = xr[i] * scale * w[i];
        __nv_bfloat16 h, l; hilo(v, h, l);
        g_XNhi[(size_t)row * DM + i] = h;
        g_XNlo[(size_t)row * DM + i] = l;
    }
}

// ---------------- fused conv + acs (fast-math exp) ----------------
#define CONV_BLOCKS ((ROWS*CONVCH)/256)   // 36864 exact

__global__ void k_conv_acs(const float* __restrict__ zx, float* __restrict__ xBC,
                           const float* __restrict__ conv_w, const float* __restrict__ conv_b,
                           const float* __restrict__ dt_bias, const float* __restrict__ A_log,
                           float* __restrict__ dt, float* __restrict__ Acs) {
    int tid = threadIdx.x;
    if (blockIdx.x < CONV_BLOCKS) {
        int idx = blockIdx.x * 256 + tid;
        int ch = idx % CONVCH;
        int r = idx / CONVCH;
        int l = r & (SEQL - 1);
        float acc = conv_b[ch];
#pragma unroll
        for (int k = 0; k < 4; k++) {
            int ll = l - 3 + k;
            if (ll >= 0)
                acc += zx[(size_t)(r - 3 + k) * DPROJ + DIN + ch] * conv_w[ch * 4 + k];
        }
        xBC[idx] = acc / (1.f + __expf(-acc));
    } else {
        int bb = blockIdx.x - CONV_BLOCKS;
        int c = bb % NCHUNK;
        int h = (bb / NCHUNK) % NH;
        int b = bb / (NCHUNK * NH);
        int l = tid;
        __shared__ float wsum[4];
        float x = 0.f;
        if (l < 128) {
            int row = b * SEQL + c * CH + l;
            float v = zx[(size_t)row * DPROJ + DIN + CONVCH + h] + dt_bias[h];
            float dtv = (v > 20.f) ? v : log1pf(__expf(v));
            dt[row * NH + h] = dtv;
            float Aneg = -__expf(A_log[h]);
            x = Aneg * dtv;
            for (int o = 1; o < 32; o <<= 1) {
                float t = __shfl_up_sync(0xffffffffu, x, o);
                if ((l & 31) >= o) x += t;
            }
            if ((l & 31) == 31) wsum[l >> 5] = x;
        }
        __syncthreads();
        if (l < 128) {
            float add = 0.f;
            int w = l >> 5;
            for (int i = 0; i < w; i++) add += wsum[i];
            Acs[(b * NH + h) * SEQL + c * CH + l] = x + add;
        }
    }
}

// ---------------- fused states + cb: states branch on HMMA ----------------
#define CB_BLOCKS (BATCH*NCHUNK)   // 32

__global__ void __launch_bounds__(256) k_states_cb(
    const float* __restrict__ xBC, const float* __restrict__ dt,
    const float* __restrict__ Acs, float* __restrict__ states,
    float* __restrict__ S) {
    __shared__ __align__(16) char smu[33792];
    int tid = threadIdx.x;

    if (blockIdx.x < CB_BLOCKS) {
        // ---- cb branch (SIMT; 32 blocks, hidden under states blocks) ----
        int tx = tid & 15, ty = tid >> 4;
        int c = blockIdx.x % NCHUNK, b = blockIdx.x / NCHUNK;
        float (*sC)[132]  = reinterpret_cast<float(*)[132]>(smu);
        float (*sBm)[132] = reinterpret_cast<float(*)[132]>(smu + 32 * 132 * 4);
        float acc[8][8];
#pragma unroll
        for (int i = 0; i < 8; i++)
#pragma unroll
            for (int j = 0; j < 8; j++) acc[i][j] = 0.f;

        for (int k0 = 0; k0 < DSTATE; k0 += 32) {
            for (int i = tid; i < 32 * 128; i += 256) {
                int kk = i & 31, l = i >> 5;
                int row = b * SEQL + c * CH + l;
                sC[kk][l]  = xBC[(size_t)row * CONVCH + DIN + DSTATE + k0 + kk];
                sBm[kk][l] = xBC[(size_t)row * CONVCH + DIN + k0 + kk];
            }
            __syncthreads();
#pragma unroll
            for (int kk = 0; kk < 32; kk++) {
                float a[8], bv[8];
#pragma unroll
                for (int i = 0; i < 8; i++) a[i] = sC[kk][ty * 8 + i];
#pragma unroll
                for (int j = 0; j < 8; j++) bv[j] = sBm[kk][tx * 8 + j];
#pragma unroll
                for (int i = 0; i < 8; i++)
#pragma unroll
                    for (int j = 0; j < 8; j++) acc[i][j] += a[i] * bv[j];
            }
            __syncthreads();
        }
        size_t base = (size_t)(b * NCHUNK + c) * CH * CH;
#pragma unroll
        for (int i = 0; i < 8; i++)
#pragma unroll
            for (int j = 0; j < 8; j++)
                S[base + (ty * 8 + i) * CH + tx * 8 + j] = acc[i][j];
    } else {
        // ---- states branch on HMMA ----
        // states[p(64)][n(128)] = sum_l Xw[l][p] * B[l][n], K=l in 4 slices of 32.
        // A operand: Xw^T stored [p][l]; B operand: B^T stored [n][l] (row.col mma).
        int bb = blockIdx.x - CB_BLOCKS;
        int h = bb % NH;
        int c = (bb / NH) % NCHUNK;
        int b = bb / (NH * NCHUNK);
        __nv_bfloat16* sAh = reinterpret_cast<__nv_bfloat16*>(smu);            // 64x40
        __nv_bfloat16* sAl = reinterpret_cast<__nv_bfloat16*>(smu + 5120);
        __nv_bfloat16* sBh = reinterpret_cast<__nv_bfloat16*>(smu + 10240);    // 128x40
        __nv_bfloat16* sBl = reinterpret_cast<__nv_bfloat16*>(smu + 20480);
        const uint32_t uAh = smem_u32(sAh), uAl = smem_u32(sAl);
        const uint32_t uBh = smem_u32(sBh), uBl = smem_u32(sBl);
        int lane = tid & 31, wid = tid >> 5;
        int wm = (wid & 1) * 32, wn = (wid >> 1) * 32;

        float acc[2][4][4];
#pragma unroll
        for (int i = 0; i < 2; i++)
#pragma unroll
            for (int j = 0; j < 4; j++)
#pragma unroll
                for (int k = 0; k < 4; k++) acc[i][j][k] = 0.f;

        const float* AcsRow = Acs + (b * NH + h) * SEQL + c * CH;
        float AcsLast = AcsRow[127];

        for (int lt = 0; lt < 4; lt++) {
            for (int i = tid; i < 64 * 32; i += 256) {
                int p = i & 63, l = i >> 6;
                int row = b * SEQL + c * CH + lt * 32 + l;
                float w = dt[row * NH + h] * __expf(AcsLast - AcsRow[lt * 32 + l]);
                float v = xBC[(size_t)row * CONVCH + h * HD + p] * w;
                __nv_bfloat16 hh, ll; hilo(v, hh, ll);
                sAh[p * 40 + l] = hh; sAl[p * 40 + l] = ll;
            }
            for (int i = tid; i < 128 * 32; i += 256) {
                int n = i & 127, l = i >> 7;
                int row = b * SEQL + c * CH + lt * 32 + l;
                float v = xBC[(size_t)row * CONVCH + DIN + n];
                __nv_bfloat16 hh, ll; hilo(v, hh, ll);
                sBh[n * 40 + l] = hh; sBl[n * 40 + l] = ll;
            }
            __syncthreads();
#pragma unroll
            for (int ks = 0; ks < 2; ks++) {
                uint32_t bh[4][2], bl[4][2];
#pragma unroll
                for (int p2 = 0; p2 < 2; p2++) {
                    int rr = wn + p2 * 16 + ((lane >> 4) << 3) + (lane & 7);
                    int cc = ks * 2 + ((lane >> 3) & 1);
                    uint32_t t[4];
                    LDSM4(t, uBh + (uint32_t)rr * 80u + (uint32_t)cc * 16u);
                    bh[p2 * 2][0] = t[0]; bh[p2 * 2][1] = t[1];
                    bh[p2 * 2 + 1][0] = t[2]; bh[p2 * 2 + 1][1] = t[3];
                    LDSM4(t, uBl + (uint32_t)rr * 80u + (uint32_t)cc * 16u);
                    bl[p2 * 2][0] = t[0]; bl[p2 * 2][1] = t[1];
                    bl[p2 * 2 + 1][0] = t[2]; bl[p2 * 2 + 1][1] = t[3];
                }
                int ar = lane & 15;
                int ac = ks * 2 + (lane >> 4);
#pragma unroll
                for (int mf = 0; mf < 2; mf++) {
                    uint32_t a[4];
                    LDSM4(a, uAh + (uint32_t)(wm + mf * 16 + ar) * 80u + (uint32_t)ac * 16u);
#pragma unroll
                    for (int nf = 0; nf < 4; nf++) MMA16816(acc[mf][nf], a, bh[nf]);
#pragma unroll
                    for (int nf = 0; nf < 4; nf++) MMA16816(acc[mf][nf], a, bl[nf]);
                    LDSM4(a, uAl + (uint32_t)(wm + mf * 16 + ar) * 80u + (uint32_t)ac * 16u);
#pragma unroll
                    for (int nf = 0; nf < 4; nf++) MMA16816(acc[mf][nf], a, bh[nf]);
                }
            }
            __syncthreads();
        }
        size_t base = ((size_t)(b * NCHUNK + c) * NH + h) * HD * DSTATE;
#pragma unroll
        for (int mf = 0; mf < 2; mf++) {
            int p0 = wm + mf * 16 + (lane >> 2);
            int p1 = p0 + 8;
#pragma unroll
            for (int nf = 0; nf < 4; nf++) {
                int n = wn + nf * 8 + (lane & 3) * 2;
                *reinterpret_cast<float2*>(states + base + (size_t)p0 * DSTATE + n) =
                    make_float2(acc[mf][nf][0], acc[mf][nf][1]);
                *reinterpret_cast<float2*>(states + base + (size_t)p1 * DSTATE + n) =
                    make_float2(acc[mf][nf][2], acc[mf][nf][3]);
            }
        }
    }
}

// ---------------- chunk scan (2048 blocks) ----------------
__global__ void k_scan(const float* __restrict__ Acs, const float* __restrict__ states,
                       float* __restrict__ prev) {
    int seg = blockIdx.x & 31;
    int h = (blockIdx.x >> 5) % NH;
    int b = blockIdx.x / (32 * NH);
    int e = seg * 256 + threadIdx.x;
    float s = 0.f;
    for (int c = 0; c < NCHUNK; c++) {
        float cd = __expf(Acs[(b * NH + h) * SEQL + c * CH + 127]);
        size_t base = ((size_t)(b * NCHUNK + c) * NH + h) * HD * DSTATE;
        prev[base + e] = s;
        s = s * cd + states[base + e];
    }
}

// ---------------- Y = Y_diag + Y_off + xs*D  — HMMA version ----------------
__global__ void __launch_bounds__(256) k_y(
    const float* __restrict__ xBC, const float* __restrict__ dt,
    const float* __restrict__ Acs, const float* __restrict__ prev,
    const float* __restrict__ S, float* __restrict__ y,
    const float* __restrict__ Dvec) {
    int h = blockIdx.x % NH;
    int c = (blockIdx.x / NH) % NCHUNK;
    int b = blockIdx.x / (NH * NCHUNK);

    __shared__ __align__(16) char sm[31232];
    __nv_bfloat16* sAh = reinterpret_cast<__nv_bfloat16*>(sm);            // 128x40
    __nv_bfloat16* sAl = reinterpret_cast<__nv_bfloat16*>(sm + 10240);
    __nv_bfloat16* sBh = reinterpret_cast<__nv_bfloat16*>(sm + 20480);    // 64x40
    __nv_bfloat16* sBl = reinterpret_cast<__nv_bfloat16*>(sm + 25600);
    float* sAcs = reinterpret_cast<float*>(sm + 30720);
    const uint32_t uAh = smem_u32(sAh), uAl = smem_u32(sAl);
    const uint32_t uBh = smem_u32(sBh), uBl = smem_u32(sBl);

    int tid = threadIdx.x, lane = tid & 31, wid = tid >> 5;
    int wm = (wid & 3) * 32, wn = (wid >> 2) * 32;

    if (tid < 128) sAcs[tid] = Acs[(b * NH + h) * SEQL + c * CH + tid];
    __syncthreads();

    float accA[2][4][4], accB[2][4][4];
#pragma unroll
    for (int i = 0; i < 2; i++)
#pragma unroll
        for (int j = 0; j < 4; j++)
#pragma unroll
            for (int k = 0; k < 4; k++) { accA[i][j][k] = 0.f; accB[i][j][k] = 0.f; }

    auto mma_tile = [&](float (&acc)[2][4][4]) {
#pragma unroll
        for (int ks = 0; ks < 2; ks++) {
            uint32_t bh[4][2], bl[4][2];
#pragma unroll
            for (int p2 = 0; p2 < 2; p2++) {
                int rr = wn + p2 * 16 + ((lane >> 4) << 3) + (lane & 7);
                int cc = ks * 2 + ((lane >> 3) & 1);
                uint32_t t[4];
                LDSM4(t, uBh + (uint32_t)rr * 80u + (uint32_t)cc * 16u);
                bh[p2 * 2][0] = t[0]; bh[p2 * 2][1] = t[1];
                bh[p2 * 2 + 1][0] = t[2]; bh[p2 * 2 + 1][1] = t[3];
                LDSM4(t, uBl + (uint32_t)rr * 80u + (uint32_t)cc * 16u);
                bl[p2 * 2][0] = t[0]; bl[p2 * 2][1] = t[1];
                bl[p2 * 2 + 1][0] = t[2]; bl[p2 * 2 + 1][1] = t[3];
            }
            int ar = lane & 15;
            int ac = ks * 2 + (lane >> 4);
#pragma unroll
            for (int mf = 0; mf < 2; mf++) {
                uint32_t a[4];
                LDSM4(a, uAh + (uint32_t)(wm + mf * 16 + ar) * 80u + (uint32_t)ac * 16u);
#pragma unroll
                for (int nf = 0; nf < 4; nf++) MMA16816(acc[mf][nf], a, bh[nf]);
#pragma unroll
                for (int nf = 0; nf < 4; nf++) MMA16816(acc[mf][nf], a, bl[nf]);
                LDSM4(a, uAl + (uint32_t)(wm + mf * 16 + ar) * 80u + (uint32_t)ac * 16u);
#pragma unroll
                for (int nf = 0; nf < 4; nf++) MMA16816(acc[mf][nf], a, bh[nf]);
            }
        }
    };

    size_t Sbase = (size_t)(b * NCHUNK + c) * CH * CH;
    // ---- phase A: Y_diag = G @ Xdt ----
    for (int st = 0; st < 4; st++) {
        for (int i = tid; i < 128 * 32; i += 256) {
            int s = i & 31, l = i >> 5;
            int sg = st * 32 + s;
            float v = (sg <= l) ? S[Sbase + l * CH + sg] * __expf(sAcs[l] - sAcs[sg]) : 0.f;
            __nv_bfloat16 hh, ll; hilo(v, hh, ll);
            sAh[l * 40 + s] = hh; sAl[l * 40 + s] = ll;
        }
        for (int i = tid; i < 64 * 32; i += 256) {
            int p = i & 63, s = i >> 6;
            int row = b * SEQL + c * CH + st * 32 + s;
            float v = xBC[(size_t)row * CONVCH + h * HD + p] * dt[row * NH + h];
            __nv_bfloat16 hh, ll; hilo(v, hh, ll);
            sBh[p * 40 + s] = hh; sBl[p * 40 + s] = ll;
        }
        __syncthreads();
        mma_tile(accA);
        __syncthreads();
    }
    // ---- phase B: Y_off_core = Cx @ prev^T ----
    size_t Pbase = ((size_t)(b * NCHUNK + c) * NH + h) * HD * DSTATE;
    for (int nt = 0; nt < 4; nt++) {
        for (int i = tid; i < 128 * 32; i += 256) {
            int n = i & 31, l = i >> 5;
            int row = b * SEQL + c * CH + l;
            float v = xBC[(size_t)row * CONVCH + DIN + DSTATE + nt * 32 + n];
            __nv_bfloat16 hh, ll; hilo(v, hh, ll);
            sAh[l * 40 + n] = hh; sAl[l * 40 + n] = ll;
        }
        for (int i = tid; i < 64 * 32; i += 256) {
            int n = i & 31, p = i >> 5;
            float v = prev[Pbase + (size_t)p * DSTATE + nt * 32 + n];
            __nv_bfloat16 hh, ll; hilo(v, hh, ll);
            sBh[p * 40 + n] = hh; sBl[p * 40 + n] = ll;
        }
        __syncthreads();
        mma_tile(accB);
        __syncthreads();
    }

    // ---- combine + skip ----
    float Dh = Dvec[h];
#pragma unroll
    for (int mf = 0; mf < 2; mf++) {
        int r0 = wm + mf * 16 + (lane >> 2);
        int r1 = r0 + 8;
        float el0 = __expf(sAcs[r0]);
        float el1 = __expf(sAcs[r1]);
        int rg0 = b * SEQL + c * CH + r0;
        int rg1 = b * SEQL + c * CH + r1;
#pragma unroll
        for (int nf = 0; nf < 4; nf++) {
            int col = wn + nf * 8 + (lane & 3) * 2;
            float xs00 = xBC[(size_t)rg0 * CONVCH + h * HD + col];
            float xs01 = xBC[(size_t)rg0 * CONVCH + h * HD + col + 1];
            float xs10 = xBC[(size_t)rg1 * CONVCH + h * HD + col];
            float xs11 = xBC[(size_t)rg1 * CONVCH + h * HD + col + 1];
            y[(size_t)rg0 * DIN + h * HD + col]     = accA[mf][nf][0] + el0 * accB[mf][nf][0] + xs00 * Dh;
            y[(size_t)rg0 * DIN + h * HD + col + 1] = accA[mf][nf][1] + el0 * accB[mf][nf][1] + xs01 * Dh;
            y[(size_t)rg1 * DIN + h * HD + col]     = accA[mf][nf][2] + el1 * accB[mf][nf][2] + xs10 * Dh;
            y[(size_t)rg1 * DIN + h * HD + col + 1] = accA[mf][nf][3] + el1 * accB[mf][nf][3] + xs11 * Dh;
        }
    }
}

// ---------------- gated rmsnorm -> bf16 hi/lo directly (fast-math silu) ----------------
__global__ void k_gnorm(const float* __restrict__ zx, const float* __restrict__ y,
                        const float* __restrict__ gnorm_w,
                        __nv_bfloat16* __restrict__ outHi, __nv_bfloat16* __restrict__ outLo) {
    int row = blockIdx.x;
    __shared__ float st[DIN];
    __shared__ float sred[8];
    float ss = 0.f;
    for (int i = threadIdx.x; i < DIN; i += 256) {
        float z = zx[(size_t)row * DPROJ + i];
        float t = y[(size_t)row * DIN + i] * (z / (1.f + __expf(-z)));
        st[i] = t;
        ss += t * t;
    }
    for (int o = 16; o > 0; o >>= 1) ss += __shfl_xor_sync(0xffffffffu, ss, o);
    if ((threadIdx.x & 31) == 0) sred[threadIdx.x >> 5] = ss;
    __syncthreads();
    if (threadIdx.x == 0) {
        float t = 0.f;
        for (int i = 0; i < 8; i++) t += sred[i];
        sred[0] = t;
    }
    __syncthreads();
    float scale = rsqrtf(sred[0] / (float)DIN + EPSV);
    for (int i = threadIdx.x; i < DIN; i += 256) {
        float v = st[i] * scale * gnorm_w[i];
        __nv_bfloat16 h, l; hilo(v, h, l);
        outHi[(size_t)row * DIN + i] = h;
        outLo[(size_t)row * DIN + i] = l;
    }
}

// ---------------- host helpers ----------------
static void cvt(cudaStream_t st, const float* src, __nv_bfloat16* hi, __nv_bfloat16* lo,
                long nvalid, long total) {
    long blocks = (total / 8 + 255) / 256;
    k_cvt<<<(unsigned)blocks, 256, 0, st>>>(src, hi, lo, nvalid, total);
}

static void hgemm(cudaStream_t st,
                  const __nv_bfloat16* Ahi, const __nv_bfloat16* Alo, int lda, int K, int flipA,
                  const __nv_bfloat16* Whi, const __nv_bfloat16* Wlo, int ldw, int Ntot,
                  float* C, __nv_bfloat16* Chi, __nv_bfloat16* Clo, int ldc, int flipC,
                  const float* resid, const float* bias) {
    dim3 grid((Ntot + 127) / 128, ROWS / 128);
    k_hgemm<<<grid, 256, HSMEM, st>>>(Ahi, Alo, lda, K, flipA, Whi, Wlo, ldw, Ntot,
                                      C, Chi, Clo, ldc, flipC, resid, bias);
}

extern "C" void kernel_launch(void* const* d_in, const int* in_sizes, int n_in,
                              void* d_out, int out_size) {
    (void)in_sizes; (void)n_in; (void)out_size;
    const float* x         = (const float*)d_in[0];
    const float* norm_w    = (const float*)d_in[1];
    const float* out_w_blk = (const float*)d_in[2];
    const float* out_b_blk = (const float*)d_in[3];

    static cudaStream_t s2 = nullptr;
    static cudaEvent_t evA = nullptr, evB = nullptr, evC = nullptr;
    if (!s2) {
        cudaStreamCreateWithFlags(&s2, cudaStreamNonBlocking);
        cudaEventCreateWithFlags(&evA, cudaEventDisableTiming);
        cudaEventCreateWithFlags(&evB, cudaEventDisableTiming);
        cudaEventCreateWithFlags(&evC, cudaEventDisableTiming);
        cudaFuncSetAttribute(k_hgemm, cudaFuncAttributeMaxDynamicSharedMemorySize, HSMEM);
    }

    float *p_zx, *p_xBC, *p_dt, *p_Acs, *p_states, *p_prev, *p_S, *p_y;
    __nv_bfloat16 *p_XNhi, *p_XNlo, *p_Ahi, *p_Alo, *p_YChi, *p_YClo, *p_Whi, *p_Wlo;
    __nv_bfloat16 *p_WFhi, *p_WFlo;
    cudaGetSymbolAddress((void**)&p_zx,     g_zx);
    cudaGetSymbolAddress((void**)&p_xBC,    g_xBC);
    cudaGetSymbolAddress((void**)&p_dt,     g_dt);
    cudaGetSymbolAddress((void**)&p_Acs,    g_Acs);
    cudaGetSymbolAddress((void**)&p_states, g_states);
    cudaGetSymbolAddress((void**)&p_prev,   g_prev);
    cudaGetSymbolAddress((void**)&p_S,      g_S);
    cudaGetSymbolAddress((void**)&p_y,      g_y);
    cudaGetSymbolAddress((void**)&p_XNhi,   g_XNhi);
    cudaGetSymbolAddress((void**)&p_XNlo,   g_XNlo);
    cudaGetSymbolAddress((void**)&p_Ahi,    g_Ahi);
    cudaGetSymbolAddress((void**)&p_Alo,    g_Alo);
    cudaGetSymbolAddress((void**)&p_YChi,   g_YChi);
    cudaGetSymbolAddress((void**)&p_YClo,   g_YClo);
    cudaGetSymbolAddress((void**)&p_Whi,    g_Whi);
    cudaGetSymbolAddress((void**)&p_Wlo,    g_Wlo);
    cudaGetSymbolAddress((void**)&p_WFhi,   g_WFhi);
    cudaGetSymbolAddress((void**)&p_WFlo,   g_WFlo);

    k_rmsnorm<<<ROWS, 256, 0, 0>>>(x, norm_w);

    // fork: s2 joins the capture via evA BEFORE any s2 work (capture-legal order)
    cudaEventRecord(evA, 0);
    cudaStreamWaitEvent(s2, evA, 0);

    // WF weight cvt on s2 (after fork); evC gates partial-final-#1
    cvt(s2, out_w_blk, p_WFhi, p_WFlo, (long)DM * 2 * DM, (long)DM * 2 * DM);
    cudaEventRecord(evC, s2);

    for (int d = 0; d < 2; d++) {
        cudaStream_t st = (d == 0) ? (cudaStream_t)0 : s2;
        const float* in_w    = (const float*)d_in[4 + d * 8 + 0];
        const float* conv_w  = (const float*)d_in[4 + d * 8 + 1];
        const float* conv_b  = (const float*)d_in[4 + d * 8 + 2];
        const float* dt_bias = (const float*)d_in[4 + d * 8 + 3];
        const float* A_log   = (const float*)d_in[4 + d * 8 + 4];
        const float* Dv      = (const float*)d_in[4 + d * 8 + 5];
        const float* gnw     = (const float*)d_in[4 + d * 8 + 6];
        const float* out_w   = (const float*)d_in[4 + d * 8 + 7];

        float* zx     = p_zx     + (size_t)d * ROWS * DPROJ;
        float* xBC    = p_xBC    + (size_t)d * ROWS * CONVCH;
        float* dt     = p_dt     + (size_t)d * ROWS * NH;
        float* Acs    = p_Acs    + (size_t)d * BATCH * NH * SEQL;
        float* states = p_states + (size_t)d * BATCH * NCHUNK * NH * HD * DSTATE;
        float* prev   = p_prev   + (size_t)d * BATCH * NCHUNK * NH * HD * DSTATE;
        float* S      = p_S      + (size_t)d * BATCH * NCHUNK * CH * CH;
        float* y      = p_y      + (size_t)d * ROWS * DIN;
        __nv_bfloat16* Ahi = p_Ahi + (size_t)d * ROWS * DIN;
        __nv_bfloat16* Alo = p_Alo + (size_t)d * ROWS * DIN;
        __nv_bfloat16* Whi = p_Whi + (size_t)d * NPADW * DM;
        __nv_bfloat16* Wlo = p_Wlo + (size_t)d * NPADW * DM;

        cvt(st, in_w, Whi, Wlo, (long)DPROJ * DM, (long)NPADW * DM);
        hgemm(st, p_XNhi, p_XNlo, DM, DM, d, Whi, Wlo, DM, DPROJ,
              zx, nullptr, nullptr, DPROJ, 0, nullptr, nullptr);

        k_conv_acs<<<CONV_BLOCKS + BATCH * NH * NCHUNK, 256, 0, st>>>(
            zx, xBC, conv_w, conv_b, dt_bias, A_log, dt, Acs);
        k_states_cb<<<CB_BLOCKS + BATCH * NCHUNK * NH, 256, 0, st>>>(
            xBC, dt, Acs, states, S);
        k_scan<<<BATCH * NH * 32, 256, 0, st>>>(Acs, states, prev);
        k_y<<<BATCH * NCHUNK * NH, 256, 0, st>>>(xBC, dt, Acs, prev, S, y, Dv);
        k_gnorm<<<ROWS, 256, 0, st>>>(zx, y, gnw, Ahi, Alo);

        cvt(st, out_w, Whi, Wlo, (long)DM * DIN, (long)DM * DIN);
        hgemm(st, Ahi, Alo, DIN, DIN, 0, Whi, Wlo, DIN, DM,
              nullptr, p_YChi + d * DM, p_YClo + d * DM, 2 * DM, d, nullptr, nullptr);
    }

    // partial final GEMM #1 (fwd half) on stream0: overlaps dir-1 tail.
    cudaStreamWaitEvent(0, evC, 0);
    hgemm(0, p_YChi, p_YClo, 2 * DM, DM, 0, p_WFhi, p_WFlo, 2 * DM, DM,
          (float*)d_out, nullptr, nullptr, DM, 0, x, out_b_blk);

    // join with dir-1, then partial #2 (bwd half): out += Y_bwd @ W2^T
    cudaEventRecord(evB, s2);
    cudaStreamWaitEvent(0, evB, 0);
    hgemm(0, p_YChi + DM, p_YClo + DM, 2 * DM, DM, 0, p_WFhi + DM, p_WFlo + DM, 2 * DM, DM,
          (float*)d_out, nullptr, nullptr, DM, 0, (float*)d_out, nullptr);
}